// round 4
// baseline (speedup 1.0000x reference)
#include <cuda_runtime.h>
#include <cuda_fp16.h>
#include <math.h>
#include <stdint.h>
#include <stddef.h>

#define BATCH 2048
#define SEQ   64
#define CH    384
#define NH    12
#define HD    32
#define MTOT  (BATCH*SEQ)      // 131072
#define NQKV  (3*CH)           // 1152

// ---------------- static device scratch ------------------------------------
__device__ __half g_xh  [(size_t)MTOT * CH];     // fp16(x)
__device__ __half g_wqh [(size_t)NQKV * CH];     // permuted qkv_w^T hi [h*96+s*32+c][k]
__device__ __half g_wql [(size_t)NQKV * CH];     // permuted qkv_w^T lo
__device__ __half g_wph [(size_t)CH * CH];       // proj_w^T hi [n][k]
__device__ __half g_wpl [(size_t)CH * CH];       // proj_w^T lo
__device__ __half g_t   [(size_t)MTOT * CH];     // fp16 attention output
__device__ float  g_lamc[NH];

// ---------------- PTX helpers ----------------------------------------------
static __device__ __forceinline__ uint32_t smem_u32(const void* p) {
    uint32_t a;
    asm("{ .reg .u64 t; cvta.to.shared.u64 t, %1; cvt.u32.u64 %0, t; }"
        : "=r"(a) : "l"(p));
    return a;
}
static __device__ __forceinline__ void cp_async16(uint32_t dst, const void* src) {
    asm volatile("cp.async.ca.shared.global [%0], [%1], 16;"
                 :: "r"(dst), "l"(src) : "memory");
}
static __device__ __forceinline__ void cp_commit() {
    asm volatile("cp.async.commit_group;" ::: "memory");
}
template <int N>
static __device__ __forceinline__ void cp_wait() {
    asm volatile("cp.async.wait_group %0;" :: "n"(N) : "memory");
}
static __device__ __forceinline__ void ldsm_x4(uint32_t* r, uint32_t addr) {
    asm volatile("ldmatrix.sync.aligned.m8n8.x4.shared.b16 {%0,%1,%2,%3}, [%4];"
                 : "=r"(r[0]), "=r"(r[1]), "=r"(r[2]), "=r"(r[3]) : "r"(addr));
}
static __device__ __forceinline__ void mma16816(float* d, const uint32_t* a,
                                                uint32_t b0, uint32_t b1) {
    asm volatile("mma.sync.aligned.m16n8k16.row.col.f32.f16.f16.f32 "
                 "{%0,%1,%2,%3}, {%4,%5,%6,%7}, {%8,%9}, {%0,%1,%2,%3};"
                 : "+f"(d[0]), "+f"(d[1]), "+f"(d[2]), "+f"(d[3])
                 : "r"(a[0]), "r"(a[1]), "r"(a[2]), "r"(a[3]), "r"(b0), "r"(b1));
}

// ---------------------------------------------------------------------------
// Kernel P: x -> fp16; weights -> transposed (qkv also head-permuted) hi/lo
// ---------------------------------------------------------------------------
__global__ void prep_kernel(const float* __restrict__ x,
                            const float* __restrict__ qkv_w,
                            const float* __restrict__ proj_w,
                            const float* __restrict__ lk1, const float* __restrict__ lv1,
                            const float* __restrict__ lk2, const float* __restrict__ lv2)
{
    const long long XN4 = (long long)MTOT * CH / 4;
    const long long WQ  = (long long)NQKV * CH;
    const long long WP  = (long long)CH * CH;
    const long long TOT = XN4 + WQ + WP + NH;
    long long stride = (long long)gridDim.x * blockDim.x;
    for (long long i = (long long)blockIdx.x * blockDim.x + threadIdx.x;
         i < TOT; i += stride) {
        if (i < XN4) {
            float4 v = __ldg(((const float4*)x) + i);
            __half2 p0 = __floats2half2_rn(v.x, v.y);
            __half2 p1 = __floats2half2_rn(v.z, v.w);
            uint2 pk;
            pk.x = *(uint32_t*)&p0;
            pk.y = *(uint32_t*)&p1;
            ((uint2*)g_xh)[i] = pk;
        } else if (i < XN4 + WQ) {
            long long j = i - XN4;
            int np = (int)(j / CH), k = (int)(j % CH);
            int h = np / 96, rem = np % 96;
            int s = rem / 32, c = rem % 32;
            int n = s * CH + h * HD + c;       // original qkv_w column
            float w = __ldg(qkv_w + (size_t)k * NQKV + n);
            __half hh = __float2half_rn(w);
            g_wqh[j] = hh;
            g_wql[j] = __float2half_rn(w - __half2float(hh));
        } else if (i < XN4 + WQ + WP) {
            long long j = i - XN4 - WQ;
            int n = (int)(j / CH), k = (int)(j % CH);
            float w = __ldg(proj_w + (size_t)k * CH + n);
            __half h = __float2half_rn(w);
            g_wph[j] = h;
            g_wpl[j] = __float2half_rn(w - __half2float(h));
        } else {
            int h = (int)(i - XN4 - WQ - WP);
            float s1 = 0.f, s2 = 0.f;
            for (int q = 0; q < HD; q++) {
                s1 += lk1[h*HD+q] * lv1[h*HD+q];
                s2 += lk2[h*HD+q] * lv2[h*HD+q];
            }
            float lam = expf(s1) - expf(s2) + 0.35550906759096926f;
            g_lamc[h] = (1.0f - lam) * 0.1767766952966369f;
        }
    }
}

// ---------------------------------------------------------------------------
// Fused kernel: qkv GEMM (M=128, N=96, K=384) + bias + feature map +
// dual-lambda linear attention -> g_t (fp16)
// grid (12 heads, 1024 m-blocks), 256 threads (8 warps: 4m x 2n)
// ---------------------------------------------------------------------------
#define RS      40                   // smem row stride in halves (80 B)
#define TA_B    (128 * RS * 2)       // A tile bytes  (10240)
#define TB_B    (96 * RS * 2)        // B tile bytes  (7680)
#define STG_B   (TA_B + 2 * TB_B)    // stage bytes   (25600)
#define QS      100                  // qkvs row stride (floats)
#define OFF_MS  51200                // bytes
#define OFF_GT  (OFF_MS + 2 * 32 * 33 * 4)   // 59648
#define SMEM1   (OFF_GT + 128)

__global__ __launch_bounds__(256)
void qkv_attn(const __half* __restrict__ A,
              const __half* __restrict__ Wh,
              const __half* __restrict__ Wl,
              const float* __restrict__ qkv_b)
{
    extern __shared__ char smraw[];
    const uint32_t sbase = smem_u32(smraw);
    float* qkvs = (float*)smraw;                 // [128][QS]
    float* Ms   = (float*)(smraw + OFF_MS);      // [2][32*33]
    float* gtab = (float*)(smraw + OFF_GT);      // [32]

    const int tid  = threadIdx.x;
    const int lane = tid & 31;
    const int wid  = tid >> 5;
    const int wm   = wid >> 1;        // 0..3  (32 rows each)
    const int wn   = wid & 1;         // 0..1  (48 cols each)
    const int h    = blockIdx.x;
    const int arow = blockIdx.y * 128;

    if (tid < 32) gtab[tid] = expf(-2.0f * (float)(tid * tid));

    const __half* Bh = Wh + (size_t)h * 96 * CH;
    const __half* Bl = Wl + (size_t)h * 96 * CH;

    // cp.async mapping: 1280 16B transfers per stage, 5 per thread
    int ld_arr[5], ld_row[5], ld_seg[5];
    #pragma unroll
    for (int i = 0; i < 5; i++) {
        int e = tid + i * 256;            // 0..1279
        if (e < 512)      { ld_arr[i] = 0; e -= 0;   }
        else if (e < 896) { ld_arr[i] = 1; e -= 512; }
        else              { ld_arr[i] = 2; e -= 896; }
        ld_row[i] = e >> 2;
        ld_seg[i] = e & 3;
    }

    auto load_stage = [&](int c, int s) {
        const uint32_t stg = sbase + s * STG_B;
        #pragma unroll
        for (int i = 0; i < 5; i++) {
            const __half* gsrc;
            uint32_t boff;
            int row = ld_row[i];
            if (ld_arr[i] == 0)      { gsrc = A  + (size_t)(arow + row) * CH; boff = 0; }
            else if (ld_arr[i] == 1) { gsrc = Bh + (size_t)row * CH; boff = TA_B; }
            else                     { gsrc = Bl + (size_t)row * CH; boff = TA_B + TB_B; }
            gsrc += c * 32 + ld_seg[i] * 8;
            uint32_t dst = stg + boff + (row * RS + ld_seg[i] * 8) * 2;
            cp_async16(dst, gsrc);
        }
        cp_commit();
    };

    float acc[2][6][4];
    #pragma unroll
    for (int a = 0; a < 2; a++)
        #pragma unroll
        for (int b = 0; b < 6; b++)
            #pragma unroll
            for (int cdx = 0; cdx < 4; cdx++) acc[a][b][cdx] = 0.f;

    const uint32_t aBase = ((wm * 32 + (lane & 15)) * RS + (lane >> 4) * 8) * 2;
    const uint32_t bRowOff = ((wn * 48 + (lane & 7) + (lane >> 4) * 8) * RS
                              + ((lane >> 3) & 1) * 8) * 2;

    load_stage(0, 0);

    #pragma unroll 1
    for (int c = 0; c < 12; c++) {
        const int s = c & 1;
        if (c < 11) load_stage(c + 1, s ^ 1);
        if (c < 11) cp_wait<1>(); else cp_wait<0>();
        __syncthreads();

        const uint32_t stg = sbase + s * STG_B;
        #pragma unroll
        for (int ks = 0; ks < 2; ks++) {
            uint32_t afr[2][4], bhf[3][4], blf[3][4];
            #pragma unroll
            for (int mt = 0; mt < 2; mt++)
                ldsm_x4(afr[mt], stg + aBase + mt * (16 * RS * 2) + ks * 32);
            #pragma unroll
            for (int nt2 = 0; nt2 < 3; nt2++) {
                ldsm_x4(bhf[nt2], stg + TA_B + bRowOff + nt2 * (16 * RS * 2) + ks * 32);
                ldsm_x4(blf[nt2], stg + TA_B + TB_B + bRowOff + nt2 * (16 * RS * 2) + ks * 32);
            }
            #pragma unroll
            for (int mt = 0; mt < 2; mt++)
                #pragma unroll
                for (int nt = 0; nt < 6; nt++) {
                    mma16816(acc[mt][nt], afr[mt],
                             bhf[nt >> 1][(nt & 1) * 2], bhf[nt >> 1][(nt & 1) * 2 + 1]);
                    mma16816(acc[mt][nt], afr[mt],
                             blf[nt >> 1][(nt & 1) * 2], blf[nt >> 1][(nt & 1) * 2 + 1]);
                }
        }
        __syncthreads();
    }

    // ---- epilogue: bias + feature map -> qkvs smem ----
    #pragma unroll
    for (int mt = 0; mt < 2; mt++) {
        const int r0 = wm * 32 + mt * 16 + (lane >> 2);
        #pragma unroll
        for (int nt = 0; nt < 6; nt++) {
            const int c0 = wn * 48 + nt * 8 + (lane & 3) * 2;
            const int sseg = c0 >> 5;               // 0:q 1:k 2:v
            const int cc = c0 & 31;
            const int gb = sseg * CH + h * HD + cc;
            const float b0 = __ldg(qkv_b + gb), b1 = __ldg(qkv_b + gb + 1);
            #pragma unroll
            for (int hf = 0; hf < 2; hf++) {
                float v0 = acc[mt][nt][hf * 2 + 0] + b0;
                float v1 = acc[mt][nt][hf * 2 + 1] + b1;
                if (sseg > 0) {
                    v0 = (v0 >= 0.f) ? v0 + 1.f : expf(v0);
                    v1 = (v1 >= 0.f) ? v1 + 1.f : expf(v1);
                }
                qkvs[(r0 + hf * 8) * QS + c0]     = v0;
                qkvs[(r0 + hf * 8) * QS + c0 + 1] = v1;
            }
        }
    }
    __syncthreads();

    // ---- attention: threads 0-127 -> window 0, 128-255 -> window 1 ----
    const int half_ = tid >> 7;
    const int t2 = tid & 127;
    const float coef = g_lamc[h];
    const float* qb = qkvs + (half_ * 64) * QS;

    // A[d][e] * gauss * coef -> Ms
    {
        const int d  = t2 >> 2;
        const int e8 = (t2 & 3) * 8;
        float a8[8];
        #pragma unroll
        for (int j = 0; j < 8; j++) a8[j] = 0.f;
        #pragma unroll 8
        for (int n = 0; n < 64; n++) {
            float fk = qb[n * QS + 32 + d];
            #pragma unroll
            for (int j = 0; j < 8; j++)
                a8[j] += fk * qb[n * QS + 64 + e8 + j];
        }
        #pragma unroll
        for (int j = 0; j < 8; j++) {
            int e = e8 + j;
            int ad = (d > e) ? (d - e) : (e - d);
            Ms[half_ * 1056 + d * 33 + e] = a8[j] * gtab[ad] * coef;
        }
    }
    __syncthreads();

    // t = q @ M -> g_t (fp16)
    {
        const int r   = t2 >> 1;
        const int c16 = (t2 & 1) * 16;
        float a16[16];
        #pragma unroll
        for (int j = 0; j < 16; j++) a16[j] = 0.f;
        const float* Mb = Ms + half_ * 1056;
        #pragma unroll 8
        for (int d = 0; d < 32; d++) {
            float qv = qb[r * QS + d];
            #pragma unroll
            for (int j = 0; j < 16; j++)
                a16[j] += qv * Mb[d * 33 + c16 + j];
        }
        uint32_t pk[8];
        #pragma unroll
        for (int j = 0; j < 8; j++) {
            __half2 p = __floats2half2_rn(a16[2*j], a16[2*j+1]);
            pk[j] = *(uint32_t*)&p;
        }
        size_t off = ((size_t)(arow + half_ * 64 + r)) * CH + h * HD + c16;
        uint4* dh = (uint4*)(g_t + off);
        dh[0] = make_uint4(pk[0], pk[1], pk[2], pk[3]);
        dh[1] = make_uint4(pk[4], pk[5], pk[6], pk[7]);
    }
}

// ---------------------------------------------------------------------------
// proj GEMM: out[M, 384] = g_t @ proj_w + proj_b  (2-split fp16 mma)
// CTA 128x128, 8 warps (2m x 4n)
// ---------------------------------------------------------------------------
#define TILE_H2   (128 * RS)
#define STAGE_B2  (3 * TILE_H2 * 2)
#define SMEM2     (2 * STAGE_B2)

__global__ __launch_bounds__(256)
void gemm_proj(const __half* __restrict__ A,
               const __half* __restrict__ Bh,
               const __half* __restrict__ Bl,
               const float* __restrict__ bias,
               float* __restrict__ C)
{
    extern __shared__ __half sm[];
    const uint32_t sbase = smem_u32(sm);
    const int tid  = threadIdx.x;
    const int lane = tid & 31;
    const int wid  = tid >> 5;
    const int wm   = wid >> 2;
    const int wn   = wid & 3;
    const int arow = blockIdx.y * 128;
    const int brow = blockIdx.x * 128;

    int ld_arr[6], ld_row[6], ld_seg[6];
    #pragma unroll
    for (int i = 0; i < 6; i++) {
        int e = tid + i * 256;
        ld_arr[i] = e >> 9;
        int idx = e & 511;
        ld_row[i] = idx >> 2;
        ld_seg[i] = idx & 3;
    }

    auto load_stage = [&](int c, int s) {
        const uint32_t stg = sbase + s * STAGE_B2;
        #pragma unroll
        for (int i = 0; i < 6; i++) {
            const __half* gsrc;
            int row = ld_row[i];
            if (ld_arr[i] == 0)      gsrc = A  + (size_t)(arow + row) * CH;
            else if (ld_arr[i] == 1) gsrc = Bh + (size_t)(brow + row) * CH;
            else                     gsrc = Bl + (size_t)(brow + row) * CH;
            gsrc += c * 32 + ld_seg[i] * 8;
            uint32_t dst = stg + (ld_arr[i] * TILE_H2 + row * RS + ld_seg[i] * 8) * 2;
            cp_async16(dst, gsrc);
        }
        cp_commit();
    };

    float acc[4][4][4];
    #pragma unroll
    for (int a = 0; a < 4; a++)
        #pragma unroll
        for (int b = 0; b < 4; b++)
            #pragma unroll
            for (int cdx = 0; cdx < 4; cdx++) acc[a][b][cdx] = 0.f;

    const uint32_t aBase = ((wm * 64 + (lane & 15)) * RS + (lane >> 4) * 8) * 2;
    const uint32_t bRowOff = ((wn * 32 + (lane & 7) + (lane >> 4) * 8) * RS
                              + ((lane >> 3) & 1) * 8) * 2;

    load_stage(0, 0);

    #pragma unroll 1
    for (int c = 0; c < 12; c++) {
        const int s = c & 1;
        if (c < 11) load_stage(c + 1, s ^ 1);
        if (c < 11) cp_wait<1>(); else cp_wait<0>();
        __syncthreads();

        const uint32_t stg = sbase + s * STAGE_B2;
        #pragma unroll
        for (int ks = 0; ks < 2; ks++) {
            uint32_t afr[4][4], bhf[2][4], blf[2][4];
            #pragma unroll
            for (int mt = 0; mt < 4; mt++)
                ldsm_x4(afr[mt], stg + aBase + mt * (16 * RS * 2) + ks * 32);
            #pragma unroll
            for (int nt2 = 0; nt2 < 2; nt2++) {
                ldsm_x4(bhf[nt2], stg + TILE_H2 * 2 + bRowOff
                                  + nt2 * (16 * RS * 2) + ks * 32);
                ldsm_x4(blf[nt2], stg + TILE_H2 * 4 + bRowOff
                                  + nt2 * (16 * RS * 2) + ks * 32);
            }
            #pragma unroll
            for (int mt = 0; mt < 4; mt++)
                #pragma unroll
                for (int nt = 0; nt < 4; nt++) {
                    mma16816(acc[mt][nt], afr[mt],
                             bhf[nt >> 1][(nt & 1) * 2], bhf[nt >> 1][(nt & 1) * 2 + 1]);
                    mma16816(acc[mt][nt], afr[mt],
                             blf[nt >> 1][(nt & 1) * 2], blf[nt >> 1][(nt & 1) * 2 + 1]);
                }
        }
        __syncthreads();
    }

    #pragma unroll
    for (int mt = 0; mt < 4; mt++) {
        const int r0 = arow + wm * 64 + mt * 16 + (lane >> 2);
        #pragma unroll
        for (int nt = 0; nt < 4; nt++) {
            const int n = brow + wn * 32 + nt * 8 + (lane & 3) * 2;
            const float b0 = __ldg(bias + n), b1 = __ldg(bias + n + 1);
            #pragma unroll
            for (int hf = 0; hf < 2; hf++) {
                float v0 = acc[mt][nt][hf * 2 + 0] + b0;
                float v1 = acc[mt][nt][hf * 2 + 1] + b1;
                *reinterpret_cast<float2*>(
                    C + (size_t)(r0 + hf * 8) * CH + n) = make_float2(v0, v1);
            }
        }
    }
}

// ---------------------------------------------------------------------------
extern "C" void kernel_launch(void* const* d_in, const int* in_sizes, int n_in,
                              void* d_out, int out_size) {
    (void)in_sizes; (void)n_in; (void)out_size;
    const float* x      = (const float*)d_in[0];
    const float* qkv_w  = (const float*)d_in[1];
    const float* qkv_b  = (const float*)d_in[2];
    const float* proj_w = (const float*)d_in[3];
    const float* proj_b = (const float*)d_in[4];
    const float* lk1    = (const float*)d_in[5];
    const float* lv1    = (const float*)d_in[6];
    const float* lk2    = (const float*)d_in[7];
    const float* lv2    = (const float*)d_in[8];

    static int inited = 0;
    static __half *xh, *wqh, *wql, *wph, *wpl, *th;
    if (!inited) {
        cudaGetSymbolAddress((void**)&xh,  g_xh);
        cudaGetSymbolAddress((void**)&wqh, g_wqh);
        cudaGetSymbolAddress((void**)&wql, g_wql);
        cudaGetSymbolAddress((void**)&wph, g_wph);
        cudaGetSymbolAddress((void**)&wpl, g_wpl);
        cudaGetSymbolAddress((void**)&th,  g_t);
        cudaFuncSetAttribute(qkv_attn,
                             cudaFuncAttributeMaxDynamicSharedMemorySize, SMEM1);
        cudaFuncSetAttribute(gemm_proj,
                             cudaFuncAttributeMaxDynamicSharedMemorySize, SMEM2);
        inited = 1;
    }

    prep_kernel<<<2048, 256>>>(x, qkv_w, proj_w, lk1, lv1, lk2, lv2);
    qkv_attn<<<dim3(NH, MTOT/128), 256, SMEM1>>>(xh, wqh, wql, qkv_b);
    gemm_proj<<<dim3(CH/128, MTOT/128), 256, SMEM2>>>(th, wph, wpl, proj_b,
                                                      (float*)d_out);
}

// round 5
// speedup vs baseline: 1.3206x; 1.3206x over previous
#include <cuda_runtime.h>
#include <cuda_fp16.h>
#include <math.h>
#include <stdint.h>
#include <stddef.h>

#define BATCH 2048
#define SEQ   64
#define CH    384
#define NH    12
#define HD    32
#define MTOT  (BATCH*SEQ)      // 131072
#define NQKV  (3*CH)           // 1152

// ---------------- static device scratch ------------------------------------
__device__ __half g_xh  [(size_t)MTOT * CH];     // fp16(x)
__device__ __half g_wqh [(size_t)NQKV * CH];     // permuted qkv_w^T hi [h*96+s*32+c][k]
__device__ __half g_wql [(size_t)NQKV * CH];     // permuted qkv_w^T lo
__device__ __half g_wph [(size_t)CH * CH];       // proj_w^T hi [n][k]
__device__ __half g_wpl [(size_t)CH * CH];       // proj_w^T lo
__device__ __half g_t   [(size_t)MTOT * CH];     // fp16 attention output
__device__ float  g_lamc[NH];

// ---------------- PTX helpers ----------------------------------------------
static __device__ __forceinline__ uint32_t smem_u32(const void* p) {
    uint32_t a;
    asm("{ .reg .u64 t; cvta.to.shared.u64 t, %1; cvt.u32.u64 %0, t; }"
        : "=r"(a) : "l"(p));
    return a;
}
static __device__ __forceinline__ void cp_async16(uint32_t dst, const void* src) {
    asm volatile("cp.async.ca.shared.global [%0], [%1], 16;"
                 :: "r"(dst), "l"(src) : "memory");
}
static __device__ __forceinline__ void cp_commit() {
    asm volatile("cp.async.commit_group;" ::: "memory");
}
template <int N>
static __device__ __forceinline__ void cp_wait() {
    asm volatile("cp.async.wait_group %0;" :: "n"(N) : "memory");
}
static __device__ __forceinline__ void ldsm_x4(uint32_t* r, uint32_t addr) {
    asm volatile("ldmatrix.sync.aligned.m8n8.x4.shared.b16 {%0,%1,%2,%3}, [%4];"
                 : "=r"(r[0]), "=r"(r[1]), "=r"(r[2]), "=r"(r[3]) : "r"(addr));
}
static __device__ __forceinline__ void mma16816(float* d, const uint32_t* a,
                                                uint32_t b0, uint32_t b1) {
    asm volatile("mma.sync.aligned.m16n8k16.row.col.f32.f16.f16.f32 "
                 "{%0,%1,%2,%3}, {%4,%5,%6,%7}, {%8,%9}, {%0,%1,%2,%3};"
                 : "+f"(d[0]), "+f"(d[1]), "+f"(d[2]), "+f"(d[3])
                 : "r"(a[0]), "r"(a[1]), "r"(a[2]), "r"(a[3]), "r"(b0), "r"(b1));
}

// ---------------------------------------------------------------------------
// Kernel P: x -> fp16; weights -> transposed (qkv also head-permuted) hi/lo
// ---------------------------------------------------------------------------
__global__ void prep_kernel(const float* __restrict__ x,
                            const float* __restrict__ qkv_w,
                            const float* __restrict__ proj_w,
                            const float* __restrict__ lk1, const float* __restrict__ lv1,
                            const float* __restrict__ lk2, const float* __restrict__ lv2)
{
    const long long XN4 = (long long)MTOT * CH / 4;
    const long long WQ  = (long long)NQKV * CH;
    const long long WP  = (long long)CH * CH;
    const long long TOT = XN4 + WQ + WP + NH;
    long long stride = (long long)gridDim.x * blockDim.x;
    for (long long i = (long long)blockIdx.x * blockDim.x + threadIdx.x;
         i < TOT; i += stride) {
        if (i < XN4) {
            float4 v = __ldg(((const float4*)x) + i);
            __half2 p0 = __floats2half2_rn(v.x, v.y);
            __half2 p1 = __floats2half2_rn(v.z, v.w);
            uint2 pk;
            pk.x = *(uint32_t*)&p0;
            pk.y = *(uint32_t*)&p1;
            ((uint2*)g_xh)[i] = pk;
        } else if (i < XN4 + WQ) {
            long long j = i - XN4;
            int np = (int)(j / CH), k = (int)(j % CH);
            int h = np / 96, rem = np % 96;
            int s = rem / 32, c = rem % 32;
            int n = s * CH + h * HD + c;       // original qkv_w column
            float w = __ldg(qkv_w + (size_t)k * NQKV + n);
            __half hh = __float2half_rn(w);
            g_wqh[j] = hh;
            g_wql[j] = __float2half_rn(w - __half2float(hh));
        } else if (i < XN4 + WQ + WP) {
            long long j = i - XN4 - WQ;
            int n = (int)(j / CH), k = (int)(j % CH);
            float w = __ldg(proj_w + (size_t)k * CH + n);
            __half h = __float2half_rn(w);
            g_wph[j] = h;
            g_wpl[j] = __float2half_rn(w - __half2float(h));
        } else {
            int h = (int)(i - XN4 - WQ - WP);
            float s1 = 0.f, s2 = 0.f;
            for (int q = 0; q < HD; q++) {
                s1 += lk1[h*HD+q] * lv1[h*HD+q];
                s2 += lk2[h*HD+q] * lv2[h*HD+q];
            }
            float lam = expf(s1) - expf(s2) + 0.35550906759096926f;
            g_lamc[h] = (1.0f - lam) * 0.1767766952966369f;
        }
    }
}

// ---------------------------------------------------------------------------
// Fused kernel: qkv GEMM (M=128, N=96, K=384) + bias + feature map +
// tensor-core linear attention -> g_t (fp16)
// grid (12 heads, 1024 m-blocks), 256 threads (8 warps: 4m x 2n)
// ---------------------------------------------------------------------------
#define RS      40                   // GEMM smem row stride in halves (80 B)
#define TA_B    (128 * RS * 2)       // A tile bytes  (10240)
#define TB_B    (96 * RS * 2)        // B tile bytes  (7680)
#define STG_B   (TA_B + 2 * TB_B)    // stage bytes   (25600)
// attention smem (aliases the 2x25600 stage region):
#define OFF_Q   0                    // q_s  [128][40] halves  = 10240 B
#define OFF_KT  10240                // kT_s [32][136] halves  = 8704 B
#define OFF_VT  18944                // vT_s [32][136] halves  = 8704 B
#define OFF_MT  27648                // MT_s [64][40]  halves  = 5120 B
#define OFF_GT  (2 * STG_B)          // gtab [32] floats (outside stages)
#define SMEM1   (OFF_GT + 256)

__global__ __launch_bounds__(256)
void qkv_attn(const __half* __restrict__ A,
              const __half* __restrict__ Wh,
              const __half* __restrict__ Wl,
              const float* __restrict__ qkv_b)
{
    extern __shared__ char smraw[];
    const uint32_t sbase = smem_u32(smraw);
    __half* q_s  = (__half*)(smraw + OFF_Q);
    __half* kT_s = (__half*)(smraw + OFF_KT);
    __half* vT_s = (__half*)(smraw + OFF_VT);
    __half* MT_s = (__half*)(smraw + OFF_MT);
    float*  gtab = (float*)(smraw + OFF_GT);

    const int tid  = threadIdx.x;
    const int lane = tid & 31;
    const int wid  = tid >> 5;
    const int wm   = wid >> 1;        // 0..3  (32 rows each)
    const int wn   = wid & 1;         // 0..1  (48 cols each)
    const int h    = blockIdx.x;
    const int arow = blockIdx.y * 128;

    if (tid < 32) gtab[tid] = expf(-2.0f * (float)(tid * tid));

    const __half* Bh = Wh + (size_t)h * 96 * CH;
    const __half* Bl = Wl + (size_t)h * 96 * CH;

    // cp.async mapping: 1280 16B transfers per stage, 5 per thread
    int ld_arr[5], ld_row[5], ld_seg[5];
    #pragma unroll
    for (int i = 0; i < 5; i++) {
        int e = tid + i * 256;            // 0..1279
        if (e < 512)      { ld_arr[i] = 0; e -= 0;   }
        else if (e < 896) { ld_arr[i] = 1; e -= 512; }
        else              { ld_arr[i] = 2; e -= 896; }
        ld_row[i] = e >> 2;
        ld_seg[i] = e & 3;
    }

    auto load_stage = [&](int c, int s) {
        const uint32_t stg = sbase + s * STG_B;
        #pragma unroll
        for (int i = 0; i < 5; i++) {
            const __half* gsrc;
            uint32_t boff;
            int row = ld_row[i];
            if (ld_arr[i] == 0)      { gsrc = A  + (size_t)(arow + row) * CH; boff = 0; }
            else if (ld_arr[i] == 1) { gsrc = Bh + (size_t)row * CH; boff = TA_B; }
            else                     { gsrc = Bl + (size_t)row * CH; boff = TA_B + TB_B; }
            gsrc += c * 32 + ld_seg[i] * 8;
            uint32_t dst = stg + boff + (row * RS + ld_seg[i] * 8) * 2;
            cp_async16(dst, gsrc);
        }
        cp_commit();
    };

    float acc[2][6][4];
    #pragma unroll
    for (int a = 0; a < 2; a++)
        #pragma unroll
        for (int b = 0; b < 6; b++)
            #pragma unroll
            for (int cdx = 0; cdx < 4; cdx++) acc[a][b][cdx] = 0.f;

    const uint32_t aBase = ((wm * 32 + (lane & 15)) * RS + (lane >> 4) * 8) * 2;
    const uint32_t bRowOff = ((wn * 48 + (lane & 7) + (lane >> 4) * 8) * RS
                              + ((lane >> 3) & 1) * 8) * 2;

    load_stage(0, 0);

    #pragma unroll 1
    for (int c = 0; c < 12; c++) {
        const int s = c & 1;
        if (c < 11) load_stage(c + 1, s ^ 1);
        if (c < 11) cp_wait<1>(); else cp_wait<0>();
        __syncthreads();

        const uint32_t stg = sbase + s * STG_B;
        #pragma unroll
        for (int ks = 0; ks < 2; ks++) {
            uint32_t afr[2][4], bhf[3][4], blf[3][4];
            #pragma unroll
            for (int mt = 0; mt < 2; mt++)
                ldsm_x4(afr[mt], stg + aBase + mt * (16 * RS * 2) + ks * 32);
            #pragma unroll
            for (int nt2 = 0; nt2 < 3; nt2++) {
                ldsm_x4(bhf[nt2], stg + TA_B + bRowOff + nt2 * (16 * RS * 2) + ks * 32);
                ldsm_x4(blf[nt2], stg + TA_B + TB_B + bRowOff + nt2 * (16 * RS * 2) + ks * 32);
            }
            #pragma unroll
            for (int mt = 0; mt < 2; mt++)
                #pragma unroll
                for (int nt = 0; nt < 6; nt++) {
                    mma16816(acc[mt][nt], afr[mt],
                             bhf[nt >> 1][(nt & 1) * 2], bhf[nt >> 1][(nt & 1) * 2 + 1]);
                    mma16816(acc[mt][nt], afr[mt],
                             blf[nt >> 1][(nt & 1) * 2], blf[nt >> 1][(nt & 1) * 2 + 1]);
                }
        }
        __syncthreads();
    }

    // ---- epilogue: bias + feature map -> fp16 smem in mma-ready layouts ----
    // q:  q_s[token][d]      (row-major, stride 40 halves)
    // k:  kT_s[d][token]     (transposed, stride 136 halves)
    // v:  vT_s[e][token]     (transposed, stride 136 halves)
    #pragma unroll
    for (int mt = 0; mt < 2; mt++) {
        const int r0 = wm * 32 + mt * 16 + (lane >> 2);
        #pragma unroll
        for (int nt = 0; nt < 6; nt++) {
            const int c0 = wn * 48 + nt * 8 + (lane & 3) * 2;
            const int sseg = c0 >> 5;               // 0:q 1:k 2:v
            const int cc = c0 & 31;
            const int gb = sseg * CH + h * HD + cc;
            const float b0 = __ldg(qkv_b + gb), b1 = __ldg(qkv_b + gb + 1);
            #pragma unroll
            for (int hf = 0; hf < 2; hf++) {
                const int r = r0 + hf * 8;
                float v0 = acc[mt][nt][hf * 2 + 0] + b0;
                float v1 = acc[mt][nt][hf * 2 + 1] + b1;
                if (sseg == 0) {
                    __half2 p = __floats2half2_rn(v0, v1);
                    *(__half2*)&q_s[r * 40 + cc] = p;
                } else {
                    v0 = (v0 >= 0.f) ? v0 + 1.f : expf(v0);
                    v1 = (v1 >= 0.f) ? v1 + 1.f : expf(v1);
                    __half* dst = (sseg == 1) ? kT_s : vT_s;
                    dst[cc * 136 + r]       = __float2half_rn(v0);
                    dst[(cc + 1) * 136 + r] = __float2half_rn(v1);
                }
            }
        }
    }
    __syncthreads();

    // ---- attention phase: window w = wid>>2, 4 warps per window ----
    const int w  = wid >> 2;
    const int ww = wid & 3;
    const float coef = g_lamc[h];

    // A = kT @ vT^T  (m=32 d, n=32 e, k=64 tokens); warp quadrant 16x16
    {
        const int amt = ww >> 1, ant = ww & 1;
        float dA[2][4];
        #pragma unroll
        for (int i = 0; i < 2; i++)
            #pragma unroll
            for (int j = 0; j < 4; j++) dA[i][j] = 0.f;

        const uint32_t aAddr0 = sbase + OFF_KT
            + ((amt * 16 + (lane & 15)) * 136 + w * 64 + (lane >> 4) * 8) * 2;
        const uint32_t bAddr0 = sbase + OFF_VT
            + ((ant * 16 + (lane & 7) + (lane >> 4) * 8) * 136
               + w * 64 + ((lane >> 3) & 1) * 8) * 2;
        #pragma unroll
        for (int ks = 0; ks < 4; ks++) {
            uint32_t af[4], bf[4];
            ldsm_x4(af, aAddr0 + ks * 32);
            ldsm_x4(bf, bAddr0 + ks * 32);
            mma16816(dA[0], af, bf[0], bf[1]);
            mma16816(dA[1], af, bf[2], bf[3]);
        }
        // M^T[e][d] = A[d][e] * gauss(|d-e|) * coef
        #pragma unroll
        for (int n2 = 0; n2 < 2; n2++)
            #pragma unroll
            for (int idx = 0; idx < 4; idx++) {
                int d = amt * 16 + (lane >> 2) + (idx >> 1) * 8;
                int e = ant * 16 + n2 * 8 + (lane & 3) * 2 + (idx & 1);
                int ad = (d > e) ? (d - e) : (e - d);
                float val = dA[n2][idx] * gtab[ad] * coef;
                MT_s[(w * 32 + e) * 40 + d] = __float2half_rn(val);
            }
    }
    __syncthreads();

    // t = q @ M  (m=64 tokens, n=32 e, k=32 d); warp: 16 tokens
    {
        float dT[4][4];
        #pragma unroll
        for (int i = 0; i < 4; i++)
            #pragma unroll
            for (int j = 0; j < 4; j++) dT[i][j] = 0.f;

        const uint32_t qAddr0 = sbase + OFF_Q
            + ((w * 64 + ww * 16 + (lane & 15)) * 40 + (lane >> 4) * 8) * 2;
        const uint32_t mAddr0 = sbase + OFF_MT
            + ((w * 32 + (lane & 7) + (lane >> 4) * 8) * 40
               + ((lane >> 3) & 1) * 8) * 2;
        #pragma unroll
        for (int ks = 0; ks < 2; ks++) {
            uint32_t af[4];
            ldsm_x4(af, qAddr0 + ks * 32);
            #pragma unroll
            for (int ng = 0; ng < 2; ng++) {
                uint32_t bf[4];
                ldsm_x4(bf, mAddr0 + ng * (16 * 40 * 2) + ks * 32);
                mma16816(dT[ng * 2 + 0], af, bf[0], bf[1]);
                mma16816(dT[ng * 2 + 1], af, bf[2], bf[3]);
            }
        }
        #pragma unroll
        for (int nt = 0; nt < 4; nt++)
            #pragma unroll
            for (int hf = 0; hf < 2; hf++) {
                int tok = w * 64 + ww * 16 + (lane >> 2) + hf * 8;
                int e = nt * 8 + (lane & 3) * 2;
                __half2 p = __floats2half2_rn(dT[nt][hf * 2], dT[nt][hf * 2 + 1]);
                *(__half2*)&g_t[(size_t)(arow + tok) * CH + h * HD + e] = p;
            }
    }
}

// ---------------------------------------------------------------------------
// proj GEMM: out[M, 384] = g_t @ proj_w + proj_b  (2-split fp16 mma)
// CTA 128x128, 8 warps (2m x 4n)
// ---------------------------------------------------------------------------
#define TILE_H2   (128 * RS)
#define STAGE_B2  (3 * TILE_H2 * 2)
#define SMEM2     (2 * STAGE_B2)

__global__ __launch_bounds__(256)
void gemm_proj(const __half* __restrict__ A,
               const __half* __restrict__ Bh,
               const __half* __restrict__ Bl,
               const float* __restrict__ bias,
               float* __restrict__ C)
{
    extern __shared__ __half sm[];
    const uint32_t sbase = smem_u32(sm);
    const int tid  = threadIdx.x;
    const int lane = tid & 31;
    const int wid  = tid >> 5;
    const int wm   = wid >> 2;
    const int wn   = wid & 3;
    const int arow = blockIdx.y * 128;
    const int brow = blockIdx.x * 128;

    int ld_arr[6], ld_row[6], ld_seg[6];
    #pragma unroll
    for (int i = 0; i < 6; i++) {
        int e = tid + i * 256;
        ld_arr[i] = e >> 9;
        int idx = e & 511;
        ld_row[i] = idx >> 2;
        ld_seg[i] = idx & 3;
    }

    auto load_stage = [&](int c, int s) {
        const uint32_t stg = sbase + s * STAGE_B2;
        #pragma unroll
        for (int i = 0; i < 6; i++) {
            const __half* gsrc;
            int row = ld_row[i];
            if (ld_arr[i] == 0)      gsrc = A  + (size_t)(arow + row) * CH;
            else if (ld_arr[i] == 1) gsrc = Bh + (size_t)(brow + row) * CH;
            else                     gsrc = Bl + (size_t)(brow + row) * CH;
            gsrc += c * 32 + ld_seg[i] * 8;
            uint32_t dst = stg + (ld_arr[i] * TILE_H2 + row * RS + ld_seg[i] * 8) * 2;
            cp_async16(dst, gsrc);
        }
        cp_commit();
    };

    float acc[4][4][4];
    #pragma unroll
    for (int a = 0; a < 4; a++)
        #pragma unroll
        for (int b = 0; b < 4; b++)
            #pragma unroll
            for (int cdx = 0; cdx < 4; cdx++) acc[a][b][cdx] = 0.f;

    const uint32_t aBase = ((wm * 64 + (lane & 15)) * RS + (lane >> 4) * 8) * 2;
    const uint32_t bRowOff = ((wn * 32 + (lane & 7) + (lane >> 4) * 8) * RS
                              + ((lane >> 3) & 1) * 8) * 2;

    load_stage(0, 0);

    #pragma unroll 1
    for (int c = 0; c < 12; c++) {
        const int s = c & 1;
        if (c < 11) load_stage(c + 1, s ^ 1);
        if (c < 11) cp_wait<1>(); else cp_wait<0>();
        __syncthreads();

        const uint32_t stg = sbase + s * STAGE_B2;
        #pragma unroll
        for (int ks = 0; ks < 2; ks++) {
            uint32_t afr[4][4], bhf[2][4], blf[2][4];
            #pragma unroll
            for (int mt = 0; mt < 4; mt++)
                ldsm_x4(afr[mt], stg + aBase + mt * (16 * RS * 2) + ks * 32);
            #pragma unroll
            for (int nt2 = 0; nt2 < 2; nt2++) {
                ldsm_x4(bhf[nt2], stg + TILE_H2 * 2 + bRowOff
                                  + nt2 * (16 * RS * 2) + ks * 32);
                ldsm_x4(blf[nt2], stg + TILE_H2 * 4 + bRowOff
                                  + nt2 * (16 * RS * 2) + ks * 32);
            }
            #pragma unroll
            for (int mt = 0; mt < 4; mt++)
                #pragma unroll
                for (int nt = 0; nt < 4; nt++) {
                    mma16816(acc[mt][nt], afr[mt],
                             bhf[nt >> 1][(nt & 1) * 2], bhf[nt >> 1][(nt & 1) * 2 + 1]);
                    mma16816(acc[mt][nt], afr[mt],
                             blf[nt >> 1][(nt & 1) * 2], blf[nt >> 1][(nt & 1) * 2 + 1]);
                }
        }
        __syncthreads();
    }

    #pragma unroll
    for (int mt = 0; mt < 4; mt++) {
        const int r0 = arow + wm * 64 + mt * 16 + (lane >> 2);
        #pragma unroll
        for (int nt = 0; nt < 4; nt++) {
            const int n = brow + wn * 32 + nt * 8 + (lane & 3) * 2;
            const float b0 = __ldg(bias + n), b1 = __ldg(bias + n + 1);
            #pragma unroll
            for (int hf = 0; hf < 2; hf++) {
                float v0 = acc[mt][nt][hf * 2 + 0] + b0;
                float v1 = acc[mt][nt][hf * 2 + 1] + b1;
                *reinterpret_cast<float2*>(
                    C + (size_t)(r0 + hf * 8) * CH + n) = make_float2(v0, v1);
            }
        }
    }
}

// ---------------------------------------------------------------------------
extern "C" void kernel_launch(void* const* d_in, const int* in_sizes, int n_in,
                              void* d_out, int out_size) {
    (void)in_sizes; (void)n_in; (void)out_size;
    const float* x      = (const float*)d_in[0];
    const float* qkv_w  = (const float*)d_in[1];
    const float* qkv_b  = (const float*)d_in[2];
    const float* proj_w = (const float*)d_in[3];
    const float* proj_b = (const float*)d_in[4];
    const float* lk1    = (const float*)d_in[5];
    const float* lv1    = (const float*)d_in[6];
    const float* lk2    = (const float*)d_in[7];
    const float* lv2    = (const float*)d_in[8];

    static int inited = 0;
    static __half *xh, *wqh, *wql, *wph, *wpl, *th;
    if (!inited) {
        cudaGetSymbolAddress((void**)&xh,  g_xh);
        cudaGetSymbolAddress((void**)&wqh, g_wqh);
        cudaGetSymbolAddress((void**)&wql, g_wql);
        cudaGetSymbolAddress((void**)&wph, g_wph);
        cudaGetSymbolAddress((void**)&wpl, g_wpl);
        cudaGetSymbolAddress((void**)&th,  g_t);
        cudaFuncSetAttribute(qkv_attn,
                             cudaFuncAttributeMaxDynamicSharedMemorySize, SMEM1);
        cudaFuncSetAttribute(gemm_proj,
                             cudaFuncAttributeMaxDynamicSharedMemorySize, SMEM2);
        inited = 1;
    }

    prep_kernel<<<2048, 256>>>(x, qkv_w, proj_w, lk1, lv1, lk2, lv2);
    qkv_attn<<<dim3(NH, MTOT/128), 256, SMEM1>>>(xh, wqh, wql, qkv_b);
    gemm_proj<<<dim3(CH/128, MTOT/128), 256, SMEM2>>>(th, wph, wpl, proj_b,
                                                      (float*)d_out);
}

// round 7
// speedup vs baseline: 1.6267x; 1.2318x over previous
#include <cuda_runtime.h>
#include <cuda_fp16.h>
#include <math.h>
#include <stdint.h>
#include <stddef.h>

#define BATCH 2048
#define SEQ   64
#define CH    384
#define NH    12
#define HD    32
#define MTOT  (BATCH*SEQ)      // 131072
#define NQKV  (3*CH)           // 1152

// ---------------- static device scratch ------------------------------------
__device__ __half g_xh  [(size_t)MTOT * CH];     // fp16(x)
__device__ __half g_wqh [(size_t)NQKV * CH];     // permuted qkv_w^T [h*96+s*32+c][k]
__device__ __half g_wph [(size_t)CH * CH];       // proj_w^T hi [n][k]
__device__ __half g_wpl [(size_t)CH * CH];       // proj_w^T lo
__device__ __half g_t   [(size_t)MTOT * CH];     // fp16 attention output
__device__ float  g_lamc[NH];

// ---------------- PTX helpers ----------------------------------------------
static __device__ __forceinline__ uint32_t smem_u32(const void* p) {
    uint32_t a;
    asm("{ .reg .u64 t; cvta.to.shared.u64 t, %1; cvt.u32.u64 %0, t; }"
        : "=r"(a) : "l"(p));
    return a;
}
static __device__ __forceinline__ void cp_async16(uint32_t dst, const void* src) {
    asm volatile("cp.async.ca.shared.global [%0], [%1], 16;"
                 :: "r"(dst), "l"(src) : "memory");
}
static __device__ __forceinline__ void cp_commit() {
    asm volatile("cp.async.commit_group;" ::: "memory");
}
template <int N>
static __device__ __forceinline__ void cp_wait() {
    asm volatile("cp.async.wait_group %0;" :: "n"(N) : "memory");
}
static __device__ __forceinline__ void ldsm_x4(uint32_t* r, uint32_t addr) {
    asm volatile("ldmatrix.sync.aligned.m8n8.x4.shared.b16 {%0,%1,%2,%3}, [%4];"
                 : "=r"(r[0]), "=r"(r[1]), "=r"(r[2]), "=r"(r[3]) : "r"(addr));
}
static __device__ __forceinline__ void mma16816(float* d, const uint32_t* a,
                                                uint32_t b0, uint32_t b1) {
    asm volatile("mma.sync.aligned.m16n8k16.row.col.f32.f16.f16.f32 "
                 "{%0,%1,%2,%3}, {%4,%5,%6,%7}, {%8,%9}, {%0,%1,%2,%3};"
                 : "+f"(d[0]), "+f"(d[1]), "+f"(d[2]), "+f"(d[3])
                 : "r"(a[0]), "r"(a[1]), "r"(a[2]), "r"(a[3]), "r"(b0), "r"(b1));
}

// ---------------------------------------------------------------------------
// Kernel P: x -> fp16; qkv_w -> permuted/transposed fp16; proj_w -> hi/lo
// ---------------------------------------------------------------------------
__global__ void prep_kernel(const float* __restrict__ x,
                            const float* __restrict__ qkv_w,
                            const float* __restrict__ proj_w,
                            const float* __restrict__ lk1, const float* __restrict__ lv1,
                            const float* __restrict__ lk2, const float* __restrict__ lv2)
{
    const long long XN4 = (long long)MTOT * CH / 4;
    const long long WQ  = (long long)NQKV * CH;
    const long long WP  = (long long)CH * CH;
    const long long TOT = XN4 + WQ + WP + NH;
    long long stride = (long long)gridDim.x * blockDim.x;
    for (long long i = (long long)blockIdx.x * blockDim.x + threadIdx.x;
         i < TOT; i += stride) {
        if (i < XN4) {
            float4 v = __ldg(((const float4*)x) + i);
            __half2 p0 = __floats2half2_rn(v.x, v.y);
            __half2 p1 = __floats2half2_rn(v.z, v.w);
            uint2 pk;
            pk.x = *(uint32_t*)&p0;
            pk.y = *(uint32_t*)&p1;
            ((uint2*)g_xh)[i] = pk;
        } else if (i < XN4 + WQ) {
            long long j = i - XN4;
            int np = (int)(j / CH), k = (int)(j % CH);
            int h = np / 96, rem = np % 96;
            int s = rem / 32, c = rem % 32;
            int n = s * CH + h * HD + c;       // original qkv_w column
            float w = __ldg(qkv_w + (size_t)k * NQKV + n);
            g_wqh[j] = __float2half_rn(w);
        } else if (i < XN4 + WQ + WP) {
            long long j = i - XN4 - WQ;
            int n = (int)(j / CH), k = (int)(j % CH);
            float w = __ldg(proj_w + (size_t)k * CH + n);
            __half h = __float2half_rn(w);
            g_wph[j] = h;
            g_wpl[j] = __float2half_rn(w - __half2float(h));
        } else {
            int h = (int)(i - XN4 - WQ - WP);
            float s1 = 0.f, s2 = 0.f;
            for (int q = 0; q < HD; q++) {
                s1 += lk1[h*HD+q] * lv1[h*HD+q];
                s2 += lk2[h*HD+q] * lv2[h*HD+q];
            }
            float lam = expf(s1) - expf(s2) + 0.35550906759096926f;
            g_lamc[h] = (1.0f - lam) * 0.1767766952966369f;
        }
    }
}

// ---------------------------------------------------------------------------
// Fused kernel: qkv GEMM (M=128, N=96, K=384, single fp16) + bias + f-map +
// tensor-core linear attention -> g_t (fp16)
// grid (12 heads, 1024 m-blocks), 256 threads (8 warps: 4m x 2n)
// 3-stage cp.async pipeline
// ---------------------------------------------------------------------------
#define RS      40                   // GEMM smem row stride in halves (80 B)
#define TA_B    (128 * RS * 2)       // A tile bytes  (10240)
#define TB_B    (96 * RS * 2)        // B tile bytes  (7680)
#define STG1_B  (TA_B + TB_B)        // stage bytes   (17920)
// attention smem (aliases the 3x17920 stage region):
#define OFF_Q   0                    // q_s  [128][40] halves  = 10240 B
#define OFF_KT  10240                // kT_s [32][136] halves  = 8704 B
#define OFF_VT  18944                // vT_s [32][136] halves  = 8704 B
#define OFF_MT  27648                // MT_s [64][40]  halves  = 5120 B
#define OFF_GT  (3 * STG1_B)         // gtab [32] floats
#define SMEM1   (OFF_GT + 256)

__global__ __launch_bounds__(256)
void qkv_attn(const __half* __restrict__ A,
              const __half* __restrict__ Wh,
              const float* __restrict__ qkv_b)
{
    extern __shared__ char smraw[];
    const uint32_t sbase = smem_u32(smraw);
    __half* q_s  = (__half*)(smraw + OFF_Q);
    __half* kT_s = (__half*)(smraw + OFF_KT);
    __half* vT_s = (__half*)(smraw + OFF_VT);
    __half* MT_s = (__half*)(smraw + OFF_MT);
    float*  gtab = (float*)(smraw + OFF_GT);

    const int tid  = threadIdx.x;
    const int lane = tid & 31;
    const int wid  = tid >> 5;
    const int wm   = wid >> 1;        // 0..3  (32 rows each)
    const int wn   = wid & 1;         // 0..1  (48 cols each)
    const int h    = blockIdx.x;
    const int arow = blockIdx.y * 128;

    if (tid < 32) gtab[tid] = expf(-2.0f * (float)(tid * tid));

    const __half* Bh = Wh + (size_t)h * 96 * CH;

    // cp.async mapping: 896 16B transfers per stage, up to 4 per thread
    int ld_arr[4], ld_row[4], ld_seg[4], ld_on[4];
    #pragma unroll
    for (int i = 0; i < 4; i++) {
        int e = tid + i * 256;            // 0..1023
        ld_on[i] = (e < 896);
        if (e < 512) { ld_arr[i] = 0; }
        else         { ld_arr[i] = 1; e -= 512; }
        ld_row[i] = e >> 2;
        ld_seg[i] = e & 3;
    }

    auto load_stage = [&](int c, int s) {
        const uint32_t stg = sbase + s * STG1_B;
        #pragma unroll
        for (int i = 0; i < 4; i++) {
            if (!ld_on[i]) continue;
            const __half* gsrc;
            uint32_t boff;
            int row = ld_row[i];
            if (ld_arr[i] == 0) { gsrc = A  + (size_t)(arow + row) * CH; boff = 0; }
            else                { gsrc = Bh + (size_t)row * CH; boff = TA_B; }
            gsrc += c * 32 + ld_seg[i] * 8;
            uint32_t dst = stg + boff + (row * RS + ld_seg[i] * 8) * 2;
            cp_async16(dst, gsrc);
        }
        cp_commit();
    };

    float acc[2][6][4];
    #pragma unroll
    for (int a = 0; a < 2; a++)
        #pragma unroll
        for (int b = 0; b < 6; b++)
            #pragma unroll
            for (int cdx = 0; cdx < 4; cdx++) acc[a][b][cdx] = 0.f;

    const uint32_t aBase = ((wm * 32 + (lane & 15)) * RS + (lane >> 4) * 8) * 2;
    const uint32_t bRowOff = ((wn * 48 + (lane & 7) + (lane >> 4) * 8) * RS
                              + ((lane >> 3) & 1) * 8) * 2;

    load_stage(0, 0);
    load_stage(1, 1);

    #pragma unroll 1
    for (int c = 0; c < 12; c++) {
        if (c < 11) cp_wait<1>(); else cp_wait<0>();
        __syncthreads();
        if (c + 2 < 12) load_stage(c + 2, (c + 2) % 3);

        const uint32_t stg = sbase + (c % 3) * STG1_B;
        #pragma unroll
        for (int ks = 0; ks < 2; ks++) {
            uint32_t afr[2][4], bhf[3][4];
            #pragma unroll
            for (int mt = 0; mt < 2; mt++)
                ldsm_x4(afr[mt], stg + aBase + mt * (16 * RS * 2) + ks * 32);
            #pragma unroll
            for (int nt2 = 0; nt2 < 3; nt2++)
                ldsm_x4(bhf[nt2], stg + TA_B + bRowOff + nt2 * (16 * RS * 2) + ks * 32);
            #pragma unroll
            for (int mt = 0; mt < 2; mt++)
                #pragma unroll
                for (int nt = 0; nt < 6; nt++)
                    mma16816(acc[mt][nt], afr[mt],
                             bhf[nt >> 1][(nt & 1) * 2], bhf[nt >> 1][(nt & 1) * 2 + 1]);
        }
        __syncthreads();
    }

    // ---- epilogue: bias + feature map -> fp16 smem in mma-ready layouts ----
    #pragma unroll
    for (int mt = 0; mt < 2; mt++) {
        const int r0 = wm * 32 + mt * 16 + (lane >> 2);
        #pragma unroll
        for (int nt = 0; nt < 6; nt++) {
            const int c0 = wn * 48 + nt * 8 + (lane & 3) * 2;
            const int sseg = c0 >> 5;               // 0:q 1:k 2:v
            const int cc = c0 & 31;
            const int gb = sseg * CH + h * HD + cc;
            const float b0 = __ldg(qkv_b + gb), b1 = __ldg(qkv_b + gb + 1);
            #pragma unroll
            for (int hf = 0; hf < 2; hf++) {
                const int r = r0 + hf * 8;
                float v0 = acc[mt][nt][hf * 2 + 0] + b0;
                float v1 = acc[mt][nt][hf * 2 + 1] + b1;
                if (sseg == 0) {
                    __half2 p = __floats2half2_rn(v0, v1);
                    *(__half2*)&q_s[r * 40 + cc] = p;
                } else {
                    v0 = (v0 >= 0.f) ? v0 + 1.f : expf(v0);
                    v1 = (v1 >= 0.f) ? v1 + 1.f : expf(v1);
                    __half* dst = (sseg == 1) ? kT_s : vT_s;
                    dst[cc * 136 + r]       = __float2half_rn(v0);
                    dst[(cc + 1) * 136 + r] = __float2half_rn(v1);
                }
            }
        }
    }
    __syncthreads();

    // ---- attention phase: window w = wid>>2, 4 warps per window ----
    const int w  = wid >> 2;
    const int ww = wid & 3;
    const float coef = g_lamc[h];

    // A = kT @ vT^T  (m=32 d, n=32 e, k=64 tokens); warp quadrant 16x16
    {
        const int amt = ww >> 1, ant = ww & 1;
        float dA[2][4];
        #pragma unroll
        for (int i = 0; i < 2; i++)
            #pragma unroll
            for (int j = 0; j < 4; j++) dA[i][j] = 0.f;

        const uint32_t aAddr0 = sbase + OFF_KT
            + ((amt * 16 + (lane & 15)) * 136 + w * 64 + (lane >> 4) * 8) * 2;
        const uint32_t bAddr0 = sbase + OFF_VT
            + ((ant * 16 + (lane & 7) + (lane >> 4) * 8) * 136
               + w * 64 + ((lane >> 3) & 1) * 8) * 2;
        #pragma unroll
        for (int ks = 0; ks < 4; ks++) {
            uint32_t af[4], bf[4];
            ldsm_x4(af, aAddr0 + ks * 32);
            ldsm_x4(bf, bAddr0 + ks * 32);
            mma16816(dA[0], af, bf[0], bf[1]);
            mma16816(dA[1], af, bf[2], bf[3]);
        }
        // M^T[e][d] = A[d][e] * gauss(|d-e|) * coef
        #pragma unroll
        for (int n2 = 0; n2 < 2; n2++)
            #pragma unroll
            for (int idx = 0; idx < 4; idx++) {
                int d = amt * 16 + (lane >> 2) + (idx >> 1) * 8;
                int e = ant * 16 + n2 * 8 + (lane & 3) * 2 + (idx & 1);
                int ad = (d > e) ? (d - e) : (e - d);
                float val = dA[n2][idx] * gtab[ad] * coef;
                MT_s[(w * 32 + e) * 40 + d] = __float2half_rn(val);
            }
    }
    __syncthreads();

    // t = q @ M  (m=64 tokens, n=32 e, k=32 d); warp: 16 tokens
    {
        float dT[4][4];
        #pragma unroll
        for (int i = 0; i < 4; i++)
            #pragma unroll
            for (int j = 0; j < 4; j++) dT[i][j] = 0.f;

        const uint32_t qAddr0 = sbase + OFF_Q
            + ((w * 64 + ww * 16 + (lane & 15)) * 40 + (lane >> 4) * 8) * 2;
        const uint32_t mAddr0 = sbase + OFF_MT
            + ((w * 32 + (lane & 7) + (lane >> 4) * 8) * 40
               + ((lane >> 3) & 1) * 8) * 2;
        #pragma unroll
        for (int ks = 0; ks < 2; ks++) {
            uint32_t af[4];
            ldsm_x4(af, qAddr0 + ks * 32);
            #pragma unroll
            for (int ng = 0; ng < 2; ng++) {
                uint32_t bf[4];
                ldsm_x4(bf, mAddr0 + ng * (16 * 40 * 2) + ks * 32);
                mma16816(dT[ng * 2 + 0], af, bf[0], bf[1]);
                mma16816(dT[ng * 2 + 1], af, bf[2], bf[3]);
            }
        }
        #pragma unroll
        for (int nt = 0; nt < 4; nt++)
            #pragma unroll
            for (int hf = 0; hf < 2; hf++) {
                int tok = w * 64 + ww * 16 + (lane >> 2) + hf * 8;
                int e = nt * 8 + (lane & 3) * 2;
                __half2 p = __floats2half2_rn(dT[nt][hf * 2], dT[nt][hf * 2 + 1]);
                *(__half2*)&g_t[(size_t)(arow + tok) * CH + h * HD + e] = p;
            }
    }
}

// ---------------------------------------------------------------------------
// proj GEMM: out[M, 384] = g_t @ proj_w + proj_b  (2-split fp16 mma)
// CTA 128x128, 8 warps (2m x 4n), 3-stage pipeline
// ---------------------------------------------------------------------------
#define TILE_H2   (128 * RS)
#define STAGE_B2  (3 * TILE_H2 * 2)          // 30720
#define SMEM2     (3 * STAGE_B2)             // 92160

__global__ __launch_bounds__(256)
void gemm_proj(const __half* __restrict__ A,
               const __half* __restrict__ Bh,
               const __half* __restrict__ Bl,
               const float* __restrict__ bias,
               float* __restrict__ C)
{
    extern __shared__ __half sm[];
    const uint32_t sbase = smem_u32(sm);
    const int tid  = threadIdx.x;
    const int lane = tid & 31;
    const int wid  = tid >> 5;
    const int wm   = wid >> 2;
    const int wn   = wid & 3;
    const int arow = blockIdx.y * 128;
    const int brow = blockIdx.x * 128;

    int ld_arr[6], ld_row[6], ld_seg[6];
    #pragma unroll
    for (int i = 0; i < 6; i++) {
        int e = tid + i * 256;
        ld_arr[i] = e >> 9;
        int idx = e & 511;
        ld_row[i] = idx >> 2;
        ld_seg[i] = idx & 3;
    }

    auto load_stage = [&](int c, int s) {
        const uint32_t stg = sbase + s * STAGE_B2;
        #pragma unroll
        for (int i = 0; i < 6; i++) {
            const __half* gsrc;
            int row = ld_row[i];
            if (ld_arr[i] == 0)      gsrc = A  + (size_t)(arow + row) * CH;
            else if (ld_arr[i] == 1) gsrc = Bh + (size_t)(brow + row) * CH;
            else                     gsrc = Bl + (size_t)(brow + row) * CH;
            gsrc += c * 32 + ld_seg[i] * 8;
            uint32_t dst = stg + (ld_arr[i] * TILE_H2 + row * RS + ld_seg[i] * 8) * 2;
            cp_async16(dst, gsrc);
        }
        cp_commit();
    };

    float acc[4][4][4];
    #pragma unroll
    for (int a = 0; a < 4; a++)
        #pragma unroll
        for (int b = 0; b < 4; b++)
            #pragma unroll
            for (int cdx = 0; cdx < 4; cdx++) acc[a][b][cdx] = 0.f;

    const uint32_t aBase = ((wm * 64 + (lane & 15)) * RS + (lane >> 4) * 8) * 2;
    const uint32_t bRowOff = ((wn * 32 + (lane & 7) + (lane >> 4) * 8) * RS
                              + ((lane >> 3) & 1) * 8) * 2;

    load_stage(0, 0);
    load_stage(1, 1);

    #pragma unroll 1
    for (int c = 0; c < 12; c++) {
        if (c < 11) cp_wait<1>(); else cp_wait<0>();
        __syncthreads();
        if (c + 2 < 12) load_stage(c + 2, (c + 2) % 3);

        const uint32_t stg = sbase + (c % 3) * STAGE_B2;
        #pragma unroll
        for (int ks = 0; ks < 2; ks++) {
            uint32_t afr[4][4], bhf[2][4], blf[2][4];
            #pragma unroll
            for (int mt = 0; mt < 4; mt++)
                ldsm_x4(afr[mt], stg + aBase + mt * (16 * RS * 2) + ks * 32);
            #pragma unroll
            for (int nt2 = 0; nt2 < 2; nt2++) {
                ldsm_x4(bhf[nt2], stg + TILE_H2 * 2 + bRowOff
                                  + nt2 * (16 * RS * 2) + ks * 32);
                ldsm_x4(blf[nt2], stg + TILE_H2 * 4 + bRowOff
                                  + nt2 * (16 * RS * 2) + ks * 32);
            }
            #pragma unroll
            for (int mt = 0; mt < 4; mt++)
                #pragma unroll
                for (int nt = 0; nt < 4; nt++) {
                    mma16816(acc[mt][nt], afr[mt],
                             bhf[nt >> 1][(nt & 1) * 2], bhf[nt >> 1][(nt & 1) * 2 + 1]);
                    mma16816(acc[mt][nt], afr[mt],
                             blf[nt >> 1][(nt & 1) * 2], blf[nt >> 1][(nt & 1) * 2 + 1]);
                }
        }
        __syncthreads();
    }

    #pragma unroll
    for (int mt = 0; mt < 4; mt++) {
        const int r0 = arow + wm * 64 + mt * 16 + (lane >> 2);
        #pragma unroll
        for (int nt = 0; nt < 4; nt++) {
            const int n = brow + wn * 32 + nt * 8 + (lane & 3) * 2;
            const float b0 = __ldg(bias + n), b1 = __ldg(bias + n + 1);
            #pragma unroll
            for (int hf = 0; hf < 2; hf++) {
                float v0 = acc[mt][nt][hf * 2 + 0] + b0;
                float v1 = acc[mt][nt][hf * 2 + 1] + b1;
                *reinterpret_cast<float2*>(
                    C + (size_t)(r0 + hf * 8) * CH + n) = make_float2(v0, v1);
            }
        }
    }
}

// ---------------------------------------------------------------------------
extern "C" void kernel_launch(void* const* d_in, const int* in_sizes, int n_in,
                              void* d_out, int out_size) {
    (void)in_sizes; (void)n_in; (void)out_size;
    const float* x      = (const float*)d_in[0];
    const float* qkv_w  = (const float*)d_in[1];
    const float* qkv_b  = (const float*)d_in[2];
    const float* proj_w = (const float*)d_in[3];
    const float* proj_b = (const float*)d_in[4];
    const float* lk1    = (const float*)d_in[5];
    const float* lv1    = (const float*)d_in[6];
    const float* lk2    = (const float*)d_in[7];
    const float* lv2    = (const float*)d_in[8];

    static int inited = 0;
    static __half *xh, *wqh, *wph, *wpl, *th;
    if (!inited) {
        cudaGetSymbolAddress((void**)&xh,  g_xh);
        cudaGetSymbolAddress((void**)&wqh, g_wqh);
        cudaGetSymbolAddress((void**)&wph, g_wph);
        cudaGetSymbolAddress((void**)&wpl, g_wpl);
        cudaGetSymbolAddress((void**)&th,  g_t);
        cudaFuncSetAttribute(qkv_attn,
                             cudaFuncAttributeMaxDynamicSharedMemorySize, SMEM1);
        cudaFuncSetAttribute(gemm_proj,
                             cudaFuncAttributeMaxDynamicSharedMemorySize, SMEM2);
        inited = 1;
    }

    prep_kernel<<<2048, 256>>>(x, qkv_w, proj_w, lk1, lv1, lk2, lv2);
    qkv_attn<<<dim3(NH, MTOT/128), 256, SMEM1>>>(xh, wqh, qkv_b);
    gemm_proj<<<dim3(CH/128, MTOT/128), 256, SMEM2>>>(th, wph, wpl, proj_b,
                                                      (float*)d_out);
}

// round 9
// speedup vs baseline: 1.6950x; 1.0420x over previous
#include <cuda_runtime.h>
#include <cuda_fp16.h>
#include <math.h>
#include <stdint.h>
#include <stddef.h>

#define BATCH 2048
#define SEQ   64
#define CH    384
#define NH    12
#define HD    32
#define MTOT  (BATCH*SEQ)      // 131072
#define NQKV  (3*CH)           // 1152

// ---------------- static device scratch ------------------------------------
__device__ __half g_xh  [(size_t)MTOT * CH];     // fp16(x)
__device__ __half g_wqh [(size_t)NQKV * CH];     // permuted qkv_w^T [h*96+s*32+c][k]
__device__ __half g_wph [(size_t)CH * CH];       // proj_w^T [n][k]
__device__ __half g_t   [(size_t)MTOT * CH];     // fp16 attention output
__device__ float  g_lamc[NH];

// ---------------- PTX helpers ----------------------------------------------
static __device__ __forceinline__ uint32_t smem_u32(const void* p) {
    uint32_t a;
    asm("{ .reg .u64 t; cvta.to.shared.u64 t, %1; cvt.u32.u64 %0, t; }"
        : "=r"(a) : "l"(p));
    return a;
}
static __device__ __forceinline__ void cp_async16(uint32_t dst, const void* src) {
    asm volatile("cp.async.ca.shared.global [%0], [%1], 16;"
                 :: "r"(dst), "l"(src) : "memory");
}
static __device__ __forceinline__ void cp_commit() {
    asm volatile("cp.async.commit_group;" ::: "memory");
}
template <int N>
static __device__ __forceinline__ void cp_wait() {
    asm volatile("cp.async.wait_group %0;" :: "n"(N) : "memory");
}
static __device__ __forceinline__ void ldsm_x4(uint32_t* r, uint32_t addr) {
    asm volatile("ldmatrix.sync.aligned.m8n8.x4.shared.b16 {%0,%1,%2,%3}, [%4];"
                 : "=r"(r[0]), "=r"(r[1]), "=r"(r[2]), "=r"(r[3]) : "r"(addr));
}
static __device__ __forceinline__ void mma16816(float* d, const uint32_t* a,
                                                uint32_t b0, uint32_t b1) {
    asm volatile("mma.sync.aligned.m16n8k16.row.col.f32.f16.f16.f32 "
                 "{%0,%1,%2,%3}, {%4,%5,%6,%7}, {%8,%9}, {%0,%1,%2,%3};"
                 : "+f"(d[0]), "+f"(d[1]), "+f"(d[2]), "+f"(d[3])
                 : "r"(a[0]), "r"(a[1]), "r"(a[2]), "r"(a[3]), "r"(b0), "r"(b1));
}

// ---------------------------------------------------------------------------
// Kernel P: x -> fp16; qkv_w -> permuted/transposed fp16; proj_w -> transposed
// ---------------------------------------------------------------------------
__global__ void prep_kernel(const float* __restrict__ x,
                            const float* __restrict__ qkv_w,
                            const float* __restrict__ proj_w,
                            const float* __restrict__ lk1, const float* __restrict__ lv1,
                            const float* __restrict__ lk2, const float* __restrict__ lv2)
{
    const long long XN4 = (long long)MTOT * CH / 4;
    const long long WQ  = (long long)NQKV * CH;
    const long long WP  = (long long)CH * CH;
    const long long TOT = XN4 + WQ + WP + NH;
    long long stride = (long long)gridDim.x * blockDim.x;
    for (long long i = (long long)blockIdx.x * blockDim.x + threadIdx.x;
         i < TOT; i += stride) {
        if (i < XN4) {
            float4 v = __ldg(((const float4*)x) + i);
            __half2 p0 = __floats2half2_rn(v.x, v.y);
            __half2 p1 = __floats2half2_rn(v.z, v.w);
            uint2 pk;
            pk.x = *(uint32_t*)&p0;
            pk.y = *(uint32_t*)&p1;
            ((uint2*)g_xh)[i] = pk;
        } else if (i < XN4 + WQ) {
            long long j = i - XN4;
            int np = (int)(j / CH), k = (int)(j % CH);
            int h = np / 96, rem = np % 96;
            int s = rem / 32, c = rem % 32;
            int n = s * CH + h * HD + c;       // original qkv_w column
            float w = __ldg(qkv_w + (size_t)k * NQKV + n);
            g_wqh[j] = __float2half_rn(w);
        } else if (i < XN4 + WQ + WP) {
            long long j = i - XN4 - WQ;
            int n = (int)(j / CH), k = (int)(j % CH);
            float w = __ldg(proj_w + (size_t)k * CH + n);
            g_wph[j] = __float2half_rn(w);
        } else {
            int h = (int)(i - XN4 - WQ - WP);
            float s1 = 0.f, s2 = 0.f;
            for (int q = 0; q < HD; q++) {
                s1 += lk1[h*HD+q] * lv1[h*HD+q];
                s2 += lk2[h*HD+q] * lv2[h*HD+q];
            }
            float lam = expf(s1) - expf(s2) + 0.35550906759096926f;
            g_lamc[h] = (1.0f - lam) * 0.1767766952966369f;
        }
    }
}

// ---------------------------------------------------------------------------
// Fused kernel: qkv GEMM (M=128, N=96, K=384, fp16) + bias + f-map +
// tensor-core linear attention -> g_t (fp16)
// grid (12 heads, 1024 m-blocks), 256 threads (8 warps: 4m x 2n)
// 3-stage cp.async pipeline, 2 CTAs/SM
// ---------------------------------------------------------------------------
#define RS      40                   // GEMM smem row stride in halves (80 B)
#define TA_B    (128 * RS * 2)       // A tile bytes  (10240)
#define TB_B    (96 * RS * 2)        // B tile bytes  (7680)
#define STG1_B  (TA_B + TB_B)        // stage bytes   (17920)
// attention smem (aliases the 3x17920 stage region):
#define OFF_Q   0                    // q_s  [128][40] halves  = 10240 B
#define OFF_KT  10240                // kT_s [32][136] halves  = 8704 B
#define OFF_VT  18944                // vT_s [32][136] halves  = 8704 B
#define OFF_MT  27648                // MT_s [64][40]  halves  = 5120 B
#define OFF_GT  (3 * STG1_B)         // gtab [32] floats
#define SMEM1   (OFF_GT + 256)

__global__ __launch_bounds__(256, 2)
void qkv_attn(const __half* __restrict__ A,
              const __half* __restrict__ Wh,
              const float* __restrict__ qkv_b)
{
    extern __shared__ char smraw[];
    const uint32_t sbase = smem_u32(smraw);
    __half* q_s  = (__half*)(smraw + OFF_Q);
    __half* kT_s = (__half*)(smraw + OFF_KT);
    __half* vT_s = (__half*)(smraw + OFF_VT);
    __half* MT_s = (__half*)(smraw + OFF_MT);
    float*  gtab = (float*)(smraw + OFF_GT);

    const int tid  = threadIdx.x;
    const int lane = tid & 31;
    const int wid  = tid >> 5;
    const int wm   = wid >> 1;        // 0..3  (32 rows each)
    const int wn   = wid & 1;         // 0..1  (48 cols each)
    const int h    = blockIdx.x;
    const int arow = blockIdx.y * 128;

    if (tid < 32) gtab[tid] = expf(-2.0f * (float)(tid * tid));

    const __half* Bh = Wh + (size_t)h * 96 * CH;

    // cp.async mapping: 896 16B transfers per stage, up to 4 per thread
    int ld_arr[4], ld_row[4], ld_seg[4], ld_on[4];
    #pragma unroll
    for (int i = 0; i < 4; i++) {
        int e = tid + i * 256;            // 0..1023
        ld_on[i] = (e < 896);
        if (e < 512) { ld_arr[i] = 0; }
        else         { ld_arr[i] = 1; e -= 512; }
        ld_row[i] = e >> 2;
        ld_seg[i] = e & 3;
    }

    auto load_stage = [&](int c, int s) {
        const uint32_t stg = sbase + s * STG1_B;
        #pragma unroll
        for (int i = 0; i < 4; i++) {
            if (!ld_on[i]) continue;
            const __half* gsrc;
            uint32_t boff;
            int row = ld_row[i];
            if (ld_arr[i] == 0) { gsrc = A  + (size_t)(arow + row) * CH; boff = 0; }
            else                { gsrc = Bh + (size_t)row * CH; boff = TA_B; }
            gsrc += c * 32 + ld_seg[i] * 8;
            uint32_t dst = stg + boff + (row * RS + ld_seg[i] * 8) * 2;
            cp_async16(dst, gsrc);
        }
        cp_commit();
    };

    float acc[2][6][4];
    #pragma unroll
    for (int a = 0; a < 2; a++)
        #pragma unroll
        for (int b = 0; b < 6; b++)
            #pragma unroll
            for (int cdx = 0; cdx < 4; cdx++) acc[a][b][cdx] = 0.f;

    const uint32_t aBase = ((wm * 32 + (lane & 15)) * RS + (lane >> 4) * 8) * 2;
    const uint32_t bRowOff = ((wn * 48 + (lane & 7) + (lane >> 4) * 8) * RS
                              + ((lane >> 3) & 1) * 8) * 2;

    load_stage(0, 0);
    load_stage(1, 1);

    #pragma unroll 1
    for (int c = 0; c < 12; c++) {
        if (c < 11) cp_wait<1>(); else cp_wait<0>();
        __syncthreads();
        if (c + 2 < 12) load_stage(c + 2, (c + 2) % 3);

        const uint32_t stg = sbase + (c % 3) * STG1_B;
        #pragma unroll
        for (int ks = 0; ks < 2; ks++) {
            uint32_t afr[2][4], bhf[3][4];
            #pragma unroll
            for (int mt = 0; mt < 2; mt++)
                ldsm_x4(afr[mt], stg + aBase + mt * (16 * RS * 2) + ks * 32);
            #pragma unroll
            for (int nt2 = 0; nt2 < 3; nt2++)
                ldsm_x4(bhf[nt2], stg + TA_B + bRowOff + nt2 * (16 * RS * 2) + ks * 32);
            #pragma unroll
            for (int mt = 0; mt < 2; mt++)
                #pragma unroll
                for (int nt = 0; nt < 6; nt++)
                    mma16816(acc[mt][nt], afr[mt],
                             bhf[nt >> 1][(nt & 1) * 2], bhf[nt >> 1][(nt & 1) * 2 + 1]);
        }
        __syncthreads();
    }

    // ---- epilogue: bias + feature map -> fp16 smem in mma-ready layouts ----
    #pragma unroll
    for (int mt = 0; mt < 2; mt++) {
        const int r0 = wm * 32 + mt * 16 + (lane >> 2);
        #pragma unroll
        for (int nt = 0; nt < 6; nt++) {
            const int c0 = wn * 48 + nt * 8 + (lane & 3) * 2;
            const int sseg = c0 >> 5;               // 0:q 1:k 2:v
            const int cc = c0 & 31;
            const int gb = sseg * CH + h * HD + cc;
            const float b0 = __ldg(qkv_b + gb), b1 = __ldg(qkv_b + gb + 1);
            #pragma unroll
            for (int hf = 0; hf < 2; hf++) {
                const int r = r0 + hf * 8;
                float v0 = acc[mt][nt][hf * 2 + 0] + b0;
                float v1 = acc[mt][nt][hf * 2 + 1] + b1;
                if (sseg == 0) {
                    __half2 p = __floats2half2_rn(v0, v1);
                    *(__half2*)&q_s[r * 40 + cc] = p;
                } else {
                    v0 = (v0 >= 0.f) ? v0 + 1.f : expf(v0);
                    v1 = (v1 >= 0.f) ? v1 + 1.f : expf(v1);
                    __half* dst = (sseg == 1) ? kT_s : vT_s;
                    dst[cc * 136 + r]       = __float2half_rn(v0);
                    dst[(cc + 1) * 136 + r] = __float2half_rn(v1);
                }
            }
        }
    }
    __syncthreads();

    // ---- attention phase: window w = wid>>2, 4 warps per window ----
    const int w  = wid >> 2;
    const int ww = wid & 3;
    const float coef = g_lamc[h];

    // A = kT @ vT^T  (m=32 d, n=32 e, k=64 tokens); warp quadrant 16x16
    {
        const int amt = ww >> 1, ant = ww & 1;
        float dA[2][4];
        #pragma unroll
        for (int i = 0; i < 2; i++)
            #pragma unroll
            for (int j = 0; j < 4; j++) dA[i][j] = 0.f;

        const uint32_t aAddr0 = sbase + OFF_KT
            + ((amt * 16 + (lane & 15)) * 136 + w * 64 + (lane >> 4) * 8) * 2;
        const uint32_t bAddr0 = sbase + OFF_VT
            + ((ant * 16 + (lane & 7) + (lane >> 4) * 8) * 136
               + w * 64 + ((lane >> 3) & 1) * 8) * 2;
        #pragma unroll
        for (int ks = 0; ks < 4; ks++) {
            uint32_t af[4], bf[4];
            ldsm_x4(af, aAddr0 + ks * 32);
            ldsm_x4(bf, bAddr0 + ks * 32);
            mma16816(dA[0], af, bf[0], bf[1]);
            mma16816(dA[1], af, bf[2], bf[3]);
        }
        // M^T[e][d] = A[d][e] * gauss(|d-e|) * coef
        #pragma unroll
        for (int n2 = 0; n2 < 2; n2++)
            #pragma unroll
            for (int idx = 0; idx < 4; idx++) {
                int d = amt * 16 + (lane >> 2) + (idx >> 1) * 8;
                int e = ant * 16 + n2 * 8 + (lane & 3) * 2 + (idx & 1);
                int ad = (d > e) ? (d - e) : (e - d);
                float val = dA[n2][idx] * gtab[ad] * coef;
                MT_s[(w * 32 + e) * 40 + d] = __float2half_rn(val);
            }
    }
    __syncthreads();

    // t = q @ M  (m=64 tokens, n=32 e, k=32 d); warp: 16 tokens
    {
        float dT[4][4];
        #pragma unroll
        for (int i = 0; i < 4; i++)
            #pragma unroll
            for (int j = 0; j < 4; j++) dT[i][j] = 0.f;

        const uint32_t qAddr0 = sbase + OFF_Q
            + ((w * 64 + ww * 16 + (lane & 15)) * 40 + (lane >> 4) * 8) * 2;
        const uint32_t mAddr0 = sbase + OFF_MT
            + ((w * 32 + (lane & 7) + (lane >> 4) * 8) * 40
               + ((lane >> 3) & 1) * 8) * 2;
        #pragma unroll
        for (int ks = 0; ks < 2; ks++) {
            uint32_t af[4];
            ldsm_x4(af, qAddr0 + ks * 32);
            #pragma unroll
            for (int ng = 0; ng < 2; ng++) {
                uint32_t bf[4];
                ldsm_x4(bf, mAddr0 + ng * (16 * 40 * 2) + ks * 32);
                mma16816(dT[ng * 2 + 0], af, bf[0], bf[1]);
                mma16816(dT[ng * 2 + 1], af, bf[2], bf[3]);
            }
        }
        #pragma unroll
        for (int nt = 0; nt < 4; nt++)
            #pragma unroll
            for (int hf = 0; hf < 2; hf++) {
                int tok = w * 64 + ww * 16 + (lane >> 2) + hf * 8;
                int e = nt * 8 + (lane & 3) * 2;
                __half2 p = __floats2half2_rn(dT[nt][hf * 2], dT[nt][hf * 2 + 1]);
                *(__half2*)&g_t[(size_t)(arow + tok) * CH + h * HD + e] = p;
            }
    }
}

// ---------------------------------------------------------------------------
// proj GEMM: out[M, 384] = g_t @ proj_w + proj_b  (single fp16 mma)
// CTA 128x128, 8 warps (2m x 4n), 3-stage pipeline, 2 CTAs/SM
// ---------------------------------------------------------------------------
#define TILE_H2   (128 * RS)
#define STAGE_B2  (2 * TILE_H2 * 2)          // 20480 (A + B)
#define SMEM2     (3 * STAGE_B2)             // 61440

__global__ __launch_bounds__(256, 2)
void gemm_proj(const __half* __restrict__ A,
               const __half* __restrict__ Bh,
               const float* __restrict__ bias,
               float* __restrict__ C)
{
    extern __shared__ __half sm[];
    const uint32_t sbase = smem_u32(sm);
    const int tid  = threadIdx.x;
    const int lane = tid & 31;
    const int wid  = tid >> 5;
    const int wm   = wid >> 2;
    const int wn   = wid & 3;
    const int arow = blockIdx.y * 128;
    const int brow = blockIdx.x * 128;

    // 1024 16B transfers per stage, 4 per thread
    int ld_arr[4], ld_row[4], ld_seg[4];
    #pragma unroll
    for (int i = 0; i < 4; i++) {
        int e = tid + i * 256;
        ld_arr[i] = e >> 9;              // 0:A 1:B
        int idx = e & 511;
        ld_row[i] = idx >> 2;
        ld_seg[i] = idx & 3;
    }

    auto load_stage = [&](int c, int s) {
        const uint32_t stg = sbase + s * STAGE_B2;
        #pragma unroll
        for (int i = 0; i < 4; i++) {
            const __half* gsrc;
            int row = ld_row[i];
            if (ld_arr[i] == 0) gsrc = A  + (size_t)(arow + row) * CH;
            else                gsrc = Bh + (size_t)(brow + row) * CH;
            gsrc += c * 32 + ld_seg[i] * 8;
            uint32_t dst = stg + (ld_arr[i] * TILE_H2 + row * RS + ld_seg[i] * 8) * 2;
            cp_async16(dst, gsrc);
        }
        cp_commit();
    };

    float acc[4][4][4];
    #pragma unroll
    for (int a = 0; a < 4; a++)
        #pragma unroll
        for (int b = 0; b < 4; b++)
            #pragma unroll
            for (int cdx = 0; cdx < 4; cdx++) acc[a][b][cdx] = 0.f;

    const uint32_t aBase = ((wm * 64 + (lane & 15)) * RS + (lane >> 4) * 8) * 2;
    const uint32_t bRowOff = ((wn * 32 + (lane & 7) + (lane >> 4) * 8) * RS
                              + ((lane >> 3) & 1) * 8) * 2;

    load_stage(0, 0);
    load_stage(1, 1);

    #pragma unroll 1
    for (int c = 0; c < 12; c++) {
        if (c < 11) cp_wait<1>(); else cp_wait<0>();
        __syncthreads();
        if (c + 2 < 12) load_stage(c + 2, (c + 2) % 3);

        const uint32_t stg = sbase + (c % 3) * STAGE_B2;
        #pragma unroll
        for (int ks = 0; ks < 2; ks++) {
            uint32_t afr[4][4], bhf[2][4];
            #pragma unroll
            for (int mt = 0; mt < 4; mt++)
                ldsm_x4(afr[mt], stg + aBase + mt * (16 * RS * 2) + ks * 32);
            #pragma unroll
            for (int nt2 = 0; nt2 < 2; nt2++)
                ldsm_x4(bhf[nt2], stg + TILE_H2 * 2 + bRowOff
                                  + nt2 * (16 * RS * 2) + ks * 32);
            #pragma unroll
            for (int mt = 0; mt < 4; mt++)
                #pragma unroll
                for (int nt = 0; nt < 4; nt++)
                    mma16816(acc[mt][nt], afr[mt],
                             bhf[nt >> 1][(nt & 1) * 2], bhf[nt >> 1][(nt & 1) * 2 + 1]);
        }
        __syncthreads();
    }

    #pragma unroll
    for (int mt = 0; mt < 4; mt++) {
        const int r0 = arow + wm * 64 + mt * 16 + (lane >> 2);
        #pragma unroll
        for (int nt = 0; nt < 4; nt++) {
            const int n = brow + wn * 32 + nt * 8 + (lane & 3) * 2;
            const float b0 = __ldg(bias + n), b1 = __ldg(bias + n + 1);
            #pragma unroll
            for (int hf = 0; hf < 2; hf++) {
                float v0 = acc[mt][nt][hf * 2 + 0] + b0;
                float v1 = acc[mt][nt][hf * 2 + 1] + b1;
                *reinterpret_cast<float2*>(
                    C + (size_t)(r0 + hf * 8) * CH + n) = make_float2(v0, v1);
            }
        }
    }
}

// ---------------------------------------------------------------------------
extern "C" void kernel_launch(void* const* d_in, const int* in_sizes, int n_in,
                              void* d_out, int out_size) {
    (void)in_sizes; (void)n_in; (void)out_size;
    const float* x      = (const float*)d_in[0];
    const float* qkv_w  = (const float*)d_in[1];
    const float* qkv_b  = (const float*)d_in[2];
    const float* proj_w = (const float*)d_in[3];
    const float* proj_b = (const float*)d_in[4];
    const float* lk1    = (const float*)d_in[5];
    const float* lv1    = (const float*)d_in[6];
    const float* lk2    = (const float*)d_in[7];
    const float* lv2    = (const float*)d_in[8];

    static int inited = 0;
    static __half *xh, *wqh, *wph, *th;
    if (!inited) {
        cudaGetSymbolAddress((void**)&xh,  g_xh);
        cudaGetSymbolAddress((void**)&wqh, g_wqh);
        cudaGetSymbolAddress((void**)&wph, g_wph);
        cudaGetSymbolAddress((void**)&th,  g_t);
        cudaFuncSetAttribute(qkv_attn,
                             cudaFuncAttributeMaxDynamicSharedMemorySize, SMEM1);
        cudaFuncSetAttribute(gemm_proj,
                             cudaFuncAttributeMaxDynamicSharedMemorySize, SMEM2);
        inited = 1;
    }

    prep_kernel<<<2048, 256>>>(x, qkv_w, proj_w, lk1, lv1, lk2, lv2);
    qkv_attn<<<dim3(NH, MTOT/128), 256, SMEM1>>>(xh, wqh, qkv_b);
    gemm_proj<<<dim3(CH/128, MTOT/128), 256, SMEM2>>>(th, wph, proj_b,
                                                      (float*)d_out);
}

// round 10
// speedup vs baseline: 1.8000x; 1.0619x over previous
#include <cuda_runtime.h>
#include <cuda_fp16.h>
#include <math.h>
#include <stdint.h>
#include <stddef.h>

#define BATCH 2048
#define SEQ   64
#define CH    384
#define NH    12
#define HD    32
#define MTOT  (BATCH*SEQ)      // 131072
#define NQKV  (3*CH)           // 1152

// ---------------- static device scratch ------------------------------------
__device__ __half g_xh  [(size_t)MTOT * CH];     // fp16(x)
__device__ __half g_wqh [(size_t)NQKV * CH];     // permuted qkv_w^T [h*96+s*32+c][k]
__device__ __half g_wph [(size_t)CH * CH];       // proj_w^T [n][k]
__device__ __half g_t   [(size_t)MTOT * CH];     // fp16 attention output
__device__ float  g_lamc[NH];

// ---------------- PTX helpers ----------------------------------------------
static __device__ __forceinline__ uint32_t smem_u32(const void* p) {
    uint32_t a;
    asm("{ .reg .u64 t; cvta.to.shared.u64 t, %1; cvt.u32.u64 %0, t; }"
        : "=r"(a) : "l"(p));
    return a;
}
static __device__ __forceinline__ void cp_async16(uint32_t dst, const void* src) {
    asm volatile("cp.async.ca.shared.global [%0], [%1], 16;"
                 :: "r"(dst), "l"(src) : "memory");
}
static __device__ __forceinline__ void cp_commit() {
    asm volatile("cp.async.commit_group;" ::: "memory");
}
template <int N>
static __device__ __forceinline__ void cp_wait() {
    asm volatile("cp.async.wait_group %0;" :: "n"(N) : "memory");
}
static __device__ __forceinline__ void ldsm_x4(uint32_t* r, uint32_t addr) {
    asm volatile("ldmatrix.sync.aligned.m8n8.x4.shared.b16 {%0,%1,%2,%3}, [%4];"
                 : "=r"(r[0]), "=r"(r[1]), "=r"(r[2]), "=r"(r[3]) : "r"(addr));
}
static __device__ __forceinline__ void mma16816(float* d, const uint32_t* a,
                                                uint32_t b0, uint32_t b1) {
    asm volatile("mma.sync.aligned.m16n8k16.row.col.f32.f16.f16.f32 "
                 "{%0,%1,%2,%3}, {%4,%5,%6,%7}, {%8,%9}, {%0,%1,%2,%3};"
                 : "+f"(d[0]), "+f"(d[1]), "+f"(d[2]), "+f"(d[3])
                 : "r"(a[0]), "r"(a[1]), "r"(a[2]), "r"(a[3]), "r"(b0), "r"(b1));
}

// ---------------------------------------------------------------------------
// Kernel P: x -> fp16; qkv_w -> permuted/transposed fp16; proj_w -> transposed
// ---------------------------------------------------------------------------
__global__ void prep_kernel(const float* __restrict__ x,
                            const float* __restrict__ qkv_w,
                            const float* __restrict__ proj_w,
                            const float* __restrict__ lk1, const float* __restrict__ lv1,
                            const float* __restrict__ lk2, const float* __restrict__ lv2)
{
    const long long XN4 = (long long)MTOT * CH / 4;
    const long long WQ  = (long long)NQKV * CH;
    const long long WP  = (long long)CH * CH;
    const long long TOT = XN4 + WQ + WP + NH;
    long long stride = (long long)gridDim.x * blockDim.x;
    for (long long i = (long long)blockIdx.x * blockDim.x + threadIdx.x;
         i < TOT; i += stride) {
        if (i < XN4) {
            float4 v = __ldg(((const float4*)x) + i);
            __half2 p0 = __floats2half2_rn(v.x, v.y);
            __half2 p1 = __floats2half2_rn(v.z, v.w);
            uint2 pk;
            pk.x = *(uint32_t*)&p0;
            pk.y = *(uint32_t*)&p1;
            ((uint2*)g_xh)[i] = pk;
        } else if (i < XN4 + WQ) {
            long long j = i - XN4;
            int np = (int)(j / CH), k = (int)(j % CH);
            int h = np / 96, rem = np % 96;
            int s = rem / 32, c = rem % 32;
            int n = s * CH + h * HD + c;       // original qkv_w column
            float w = __ldg(qkv_w + (size_t)k * NQKV + n);
            g_wqh[j] = __float2half_rn(w);
        } else if (i < XN4 + WQ + WP) {
            long long j = i - XN4 - WQ;
            int n = (int)(j / CH), k = (int)(j % CH);
            float w = __ldg(proj_w + (size_t)k * CH + n);
            g_wph[j] = __float2half_rn(w);
        } else {
            int h = (int)(i - XN4 - WQ - WP);
            float s1 = 0.f, s2 = 0.f;
            for (int q = 0; q < HD; q++) {
                s1 += lk1[h*HD+q] * lv1[h*HD+q];
                s2 += lk2[h*HD+q] * lv2[h*HD+q];
            }
            float lam = expf(s1) - expf(s2) + 0.35550906759096926f;
            g_lamc[h] = (1.0f - lam) * 0.1767766952966369f;
        }
    }
}

// ---------------------------------------------------------------------------
// Fused kernel: qkv GEMM (M=128, N=96, K=384, fp16, K-chunks of 64) +
// bias + f-map + tensor-core linear attention -> g_t (fp16)
// grid (12 heads, 1024 m-blocks), 256 threads (8 warps: 4m x 2n)
// 3-stage cp.async pipeline, single barrier per chunk, 2 CTAs/SM
// ---------------------------------------------------------------------------
#define RS      72                   // smem row stride in halves (144 B)
#define TA_B    (128 * RS * 2)       // A tile bytes  (18432)
#define TB_B    (96 * RS * 2)        // B tile bytes  (13824)
#define STG1_B  (TA_B + TB_B)        // stage bytes   (32256)
// attention smem (aliases the stage region):
#define OFF_Q   0                    // q_s  [128][40] halves  = 10240 B
#define OFF_KT  10240                // kT_s [32][136] halves  = 8704 B
#define OFF_VT  18944                // vT_s [32][136] halves  = 8704 B
#define OFF_MT  27648                // MT_s [64][40]  halves  = 5120 B
#define OFF_GT  (3 * STG1_B)         // gtab [32] floats
#define SMEM1   (OFF_GT + 256)       // 97024

__global__ __launch_bounds__(256, 2)
void qkv_attn(const __half* __restrict__ A,
              const __half* __restrict__ Wh,
              const float* __restrict__ qkv_b)
{
    extern __shared__ char smraw[];
    const uint32_t sbase = smem_u32(smraw);
    __half* q_s  = (__half*)(smraw + OFF_Q);
    __half* kT_s = (__half*)(smraw + OFF_KT);
    __half* vT_s = (__half*)(smraw + OFF_VT);
    __half* MT_s = (__half*)(smraw + OFF_MT);
    float*  gtab = (float*)(smraw + OFF_GT);

    const int tid  = threadIdx.x;
    const int lane = tid & 31;
    const int wid  = tid >> 5;
    const int wm   = wid >> 1;        // 0..3  (32 rows each)
    const int wn   = wid & 1;         // 0..1  (48 cols each)
    const int h    = blockIdx.x;
    const int arow = blockIdx.y * 128;

    if (tid < 32) gtab[tid] = expf(-2.0f * (float)(tid * tid));

    const __half* Bh = Wh + (size_t)h * 96 * CH;

    // cp.async mapping: (128+96) rows x 8 segs = 1792 transfers, 7 per thread
    int ld_arr[7], ld_row[7], ld_seg[7];
    #pragma unroll
    for (int i = 0; i < 7; i++) {
        int e = tid + i * 256;            // 0..1791
        if (e < 1024) { ld_arr[i] = 0; }
        else          { ld_arr[i] = 1; e -= 1024; }
        ld_row[i] = e >> 3;
        ld_seg[i] = e & 7;
    }

    auto load_stage = [&](int c, int s) {
        const uint32_t stg = sbase + s * STG1_B;
        #pragma unroll
        for (int i = 0; i < 7; i++) {
            const __half* gsrc;
            uint32_t boff;
            int row = ld_row[i];
            if (ld_arr[i] == 0) { gsrc = A  + (size_t)(arow + row) * CH; boff = 0; }
            else                { gsrc = Bh + (size_t)row * CH; boff = TA_B; }
            gsrc += c * 64 + ld_seg[i] * 8;
            uint32_t dst = stg + boff + (row * RS + ld_seg[i] * 8) * 2;
            cp_async16(dst, gsrc);
        }
        cp_commit();
    };

    float acc[2][6][4];
    #pragma unroll
    for (int a = 0; a < 2; a++)
        #pragma unroll
        for (int b = 0; b < 6; b++)
            #pragma unroll
            for (int cdx = 0; cdx < 4; cdx++) acc[a][b][cdx] = 0.f;

    const uint32_t aBase = ((wm * 32 + (lane & 15)) * RS + (lane >> 4) * 8) * 2;
    const uint32_t bRowOff = ((wn * 48 + (lane & 7) + (lane >> 4) * 8) * RS
                              + ((lane >> 3) & 1) * 8) * 2;

    load_stage(0, 0);
    load_stage(1, 1);

    #pragma unroll 1
    for (int c = 0; c < 6; c++) {
        if (c < 5) cp_wait<1>(); else cp_wait<0>();
        __syncthreads();
        if (c + 2 < 6) load_stage(c + 2, (c + 2) % 3);

        const uint32_t stg = sbase + (c % 3) * STG1_B;
        #pragma unroll
        for (int ks = 0; ks < 4; ks++) {
            uint32_t afr[2][4], bhf[3][4];
            #pragma unroll
            for (int mt = 0; mt < 2; mt++)
                ldsm_x4(afr[mt], stg + aBase + mt * (16 * RS * 2) + ks * 32);
            #pragma unroll
            for (int nt2 = 0; nt2 < 3; nt2++)
                ldsm_x4(bhf[nt2], stg + TA_B + bRowOff + nt2 * (16 * RS * 2) + ks * 32);
            #pragma unroll
            for (int mt = 0; mt < 2; mt++)
                #pragma unroll
                for (int nt = 0; nt < 6; nt++)
                    mma16816(acc[mt][nt], afr[mt],
                             bhf[nt >> 1][(nt & 1) * 2], bhf[nt >> 1][(nt & 1) * 2 + 1]);
        }
        // no bottom barrier: the next iteration's top barrier orders the
        // overwrite of stage c%3 (loaded at iteration c+1) after this mma
    }
    __syncthreads();

    // ---- epilogue: bias + feature map -> fp16 smem in mma-ready layouts ----
    #pragma unroll
    for (int mt = 0; mt < 2; mt++) {
        const int r0 = wm * 32 + mt * 16 + (lane >> 2);
        #pragma unroll
        for (int nt = 0; nt < 6; nt++) {
            const int c0 = wn * 48 + nt * 8 + (lane & 3) * 2;
            const int sseg = c0 >> 5;               // 0:q 1:k 2:v
            const int cc = c0 & 31;
            const int gb = sseg * CH + h * HD + cc;
            const float b0 = __ldg(qkv_b + gb), b1 = __ldg(qkv_b + gb + 1);
            #pragma unroll
            for (int hf = 0; hf < 2; hf++) {
                const int r = r0 + hf * 8;
                float v0 = acc[mt][nt][hf * 2 + 0] + b0;
                float v1 = acc[mt][nt][hf * 2 + 1] + b1;
                if (sseg == 0) {
                    __half2 p = __floats2half2_rn(v0, v1);
                    *(__half2*)&q_s[r * 40 + cc] = p;
                } else {
                    v0 = (v0 >= 0.f) ? v0 + 1.f : expf(v0);
                    v1 = (v1 >= 0.f) ? v1 + 1.f : expf(v1);
                    __half* dst = (sseg == 1) ? kT_s : vT_s;
                    dst[cc * 136 + r]       = __float2half_rn(v0);
                    dst[(cc + 1) * 136 + r] = __float2half_rn(v1);
                }
            }
        }
    }
    __syncthreads();

    // ---- attention phase: window w = wid>>2, 4 warps per window ----
    const int w  = wid >> 2;
    const int ww = wid & 3;
    const float coef = g_lamc[h];

    // A = kT @ vT^T  (m=32 d, n=32 e, k=64 tokens); warp quadrant 16x16
    {
        const int amt = ww >> 1, ant = ww & 1;
        float dA[2][4];
        #pragma unroll
        for (int i = 0; i < 2; i++)
            #pragma unroll
            for (int j = 0; j < 4; j++) dA[i][j] = 0.f;

        const uint32_t aAddr0 = sbase + OFF_KT
            + ((amt * 16 + (lane & 15)) * 136 + w * 64 + (lane >> 4) * 8) * 2;
        const uint32_t bAddr0 = sbase + OFF_VT
            + ((ant * 16 + (lane & 7) + (lane >> 4) * 8) * 136
               + w * 64 + ((lane >> 3) & 1) * 8) * 2;
        #pragma unroll
        for (int ks = 0; ks < 4; ks++) {
            uint32_t af[4], bf[4];
            ldsm_x4(af, aAddr0 + ks * 32);
            ldsm_x4(bf, bAddr0 + ks * 32);
            mma16816(dA[0], af, bf[0], bf[1]);
            mma16816(dA[1], af, bf[2], bf[3]);
        }
        // M^T[e][d] = A[d][e] * gauss(|d-e|) * coef
        #pragma unroll
        for (int n2 = 0; n2 < 2; n2++)
            #pragma unroll
            for (int idx = 0; idx < 4; idx++) {
                int d = amt * 16 + (lane >> 2) + (idx >> 1) * 8;
                int e = ant * 16 + n2 * 8 + (lane & 3) * 2 + (idx & 1);
                int ad = (d > e) ? (d - e) : (e - d);
                float val = dA[n2][idx] * gtab[ad] * coef;
                MT_s[(w * 32 + e) * 40 + d] = __float2half_rn(val);
            }
    }
    __syncthreads();

    // t = q @ M  (m=64 tokens, n=32 e, k=32 d); warp: 16 tokens
    {
        float dT[4][4];
        #pragma unroll
        for (int i = 0; i < 4; i++)
            #pragma unroll
            for (int j = 0; j < 4; j++) dT[i][j] = 0.f;

        const uint32_t qAddr0 = sbase + OFF_Q
            + ((w * 64 + ww * 16 + (lane & 15)) * 40 + (lane >> 4) * 8) * 2;
        const uint32_t mAddr0 = sbase + OFF_MT
            + ((w * 32 + (lane & 7) + (lane >> 4) * 8) * 40
               + ((lane >> 3) & 1) * 8) * 2;
        #pragma unroll
        for (int ks = 0; ks < 2; ks++) {
            uint32_t af[4];
            ldsm_x4(af, qAddr0 + ks * 32);
            #pragma unroll
            for (int ng = 0; ng < 2; ng++) {
                uint32_t bf[4];
                ldsm_x4(bf, mAddr0 + ng * (16 * 40 * 2) + ks * 32);
                mma16816(dT[ng * 2 + 0], af, bf[0], bf[1]);
                mma16816(dT[ng * 2 + 1], af, bf[2], bf[3]);
            }
        }
        #pragma unroll
        for (int nt = 0; nt < 4; nt++)
            #pragma unroll
            for (int hf = 0; hf < 2; hf++) {
                int tok = w * 64 + ww * 16 + (lane >> 2) + hf * 8;
                int e = nt * 8 + (lane & 3) * 2;
                __half2 p = __floats2half2_rn(dT[nt][hf * 2], dT[nt][hf * 2 + 1]);
                *(__half2*)&g_t[(size_t)(arow + tok) * CH + h * HD + e] = p;
            }
    }
}

// ---------------------------------------------------------------------------
// proj GEMM: out[M, 384] = g_t @ proj_w + proj_b  (fp16 mma, K-chunks of 64)
// CTA 128x128, 8 warps (2m x 4n), 3-stage pipeline, single barrier, 2 CTAs/SM
// ---------------------------------------------------------------------------
#define TILE_H2   (128 * RS)
#define STAGE_B2  (2 * TILE_H2 * 2)          // 36864 (A + B)
#define SMEM2     (3 * STAGE_B2)             // 110592

__global__ __launch_bounds__(256, 2)
void gemm_proj(const __half* __restrict__ A,
               const __half* __restrict__ Bh,
               const float* __restrict__ bias,
               float* __restrict__ C)
{
    extern __shared__ __half sm[];
    const uint32_t sbase = smem_u32(sm);
    const int tid  = threadIdx.x;
    const int lane = tid & 31;
    const int wid  = tid >> 5;
    const int wm   = wid >> 2;
    const int wn   = wid & 3;
    const int arow = blockIdx.y * 128;
    const int brow = blockIdx.x * 128;

    // 256 rows x 8 segs = 2048 transfers per stage, 8 per thread
    int ld_arr[8], ld_row[8], ld_seg[8];
    #pragma unroll
    for (int i = 0; i < 8; i++) {
        int e = tid + i * 256;
        ld_arr[i] = e >> 10;             // 0:A 1:B
        int idx = e & 1023;
        ld_row[i] = idx >> 3;
        ld_seg[i] = idx & 7;
    }

    auto load_stage = [&](int c, int s) {
        const uint32_t stg = sbase + s * STAGE_B2;
        #pragma unroll
        for (int i = 0; i < 8; i++) {
            const __half* gsrc;
            int row = ld_row[i];
            if (ld_arr[i] == 0) gsrc = A  + (size_t)(arow + row) * CH;
            else                gsrc = Bh + (size_t)(brow + row) * CH;
            gsrc += c * 64 + ld_seg[i] * 8;
            uint32_t dst = stg + (ld_arr[i] * TILE_H2 + row * RS + ld_seg[i] * 8) * 2;
            cp_async16(dst, gsrc);
        }
        cp_commit();
    };

    float acc[4][4][4];
    #pragma unroll
    for (int a = 0; a < 4; a++)
        #pragma unroll
        for (int b = 0; b < 4; b++)
            #pragma unroll
            for (int cdx = 0; cdx < 4; cdx++) acc[a][b][cdx] = 0.f;

    const uint32_t aBase = ((wm * 64 + (lane & 15)) * RS + (lane >> 4) * 8) * 2;
    const uint32_t bRowOff = ((wn * 32 + (lane & 7) + (lane >> 4) * 8) * RS
                              + ((lane >> 3) & 1) * 8) * 2;

    load_stage(0, 0);
    load_stage(1, 1);

    #pragma unroll 1
    for (int c = 0; c < 6; c++) {
        if (c < 5) cp_wait<1>(); else cp_wait<0>();
        __syncthreads();
        if (c + 2 < 6) load_stage(c + 2, (c + 2) % 3);

        const uint32_t stg = sbase + (c % 3) * STAGE_B2;
        #pragma unroll
        for (int ks = 0; ks < 4; ks++) {
            uint32_t afr[4][4], bhf[2][4];
            #pragma unroll
            for (int mt = 0; mt < 4; mt++)
                ldsm_x4(afr[mt], stg + aBase + mt * (16 * RS * 2) + ks * 32);
            #pragma unroll
            for (int nt2 = 0; nt2 < 2; nt2++)
                ldsm_x4(bhf[nt2], stg + TILE_H2 * 2 + bRowOff
                                  + nt2 * (16 * RS * 2) + ks * 32);
            #pragma unroll
            for (int mt = 0; mt < 4; mt++)
                #pragma unroll
                for (int nt = 0; nt < 4; nt++)
                    mma16816(acc[mt][nt], afr[mt],
                             bhf[nt >> 1][(nt & 1) * 2], bhf[nt >> 1][(nt & 1) * 2 + 1]);
        }
    }

    #pragma unroll
    for (int mt = 0; mt < 4; mt++) {
        const int r0 = arow + wm * 64 + mt * 16 + (lane >> 2);
        #pragma unroll
        for (int nt = 0; nt < 4; nt++) {
            const int n = brow + wn * 32 + nt * 8 + (lane & 3) * 2;
            const float b0 = __ldg(bias + n), b1 = __ldg(bias + n + 1);
            #pragma unroll
            for (int hf = 0; hf < 2; hf++) {
                float v0 = acc[mt][nt][hf * 2 + 0] + b0;
                float v1 = acc[mt][nt][hf * 2 + 1] + b1;
                *reinterpret_cast<float2*>(
                    C + (size_t)(r0 + hf * 8) * CH + n) = make_float2(v0, v1);
            }
        }
    }
}

// ---------------------------------------------------------------------------
extern "C" void kernel_launch(void* const* d_in, const int* in_sizes, int n_in,
                              void* d_out, int out_size) {
    (void)in_sizes; (void)n_in; (void)out_size;
    const float* x      = (const float*)d_in[0];
    const float* qkv_w  = (const float*)d_in[1];
    const float* qkv_b  = (const float*)d_in[2];
    const float* proj_w = (const float*)d_in[3];
    const float* proj_b = (const float*)d_in[4];
    const float* lk1    = (const float*)d_in[5];
    const float* lv1    = (const float*)d_in[6];
    const float* lk2    = (const float*)d_in[7];
    const float* lv2    = (const float*)d_in[8];

    static int inited = 0;
    static __half *xh, *wqh, *wph, *th;
    if (!inited) {
        cudaGetSymbolAddress((void**)&xh,  g_xh);
        cudaGetSymbolAddress((void**)&wqh, g_wqh);
        cudaGetSymbolAddress((void**)&wph, g_wph);
        cudaGetSymbolAddress((void**)&th,  g_t);
        cudaFuncSetAttribute(qkv_attn,
                             cudaFuncAttributeMaxDynamicSharedMemorySize, SMEM1);
        cudaFuncSetAttribute(gemm_proj,
                             cudaFuncAttributeMaxDynamicSharedMemorySize, SMEM2);
        inited = 1;
    }

    prep_kernel<<<2048, 256>>>(x, qkv_w, proj_w, lk1, lv1, lk2, lv2);
    qkv_attn<<<dim3(NH, MTOT/128), 256, SMEM1>>>(xh, wqh, qkv_b);
    gemm_proj<<<dim3(CH/128, MTOT/128), 256, SMEM2>>>(th, wph, proj_b,
                                                      (float*)d_out);
}